// round 2
// baseline (speedup 1.0000x reference)
#include <cuda_runtime.h>
#include <cuda_bf16.h>
#include <cstdint>

#define B_ 8
#define T_ 1024
#define D_ 512
#define H_ 8
#define DK_ 64

// Scratch (static __device__ — no allocation allowed)
__device__ float g_Q2[(size_t)B_ * H_ * T_ * 128];  // [b,h,t, 0:64]=q+u, [64:128]=q+v
__device__ float g_K [(size_t)B_ * H_ * T_ * DK_];
__device__ float g_V [(size_t)B_ * H_ * T_ * DK_];
__device__ float g_P [(size_t)H_ * T_ * DK_];
__device__ float g_ctx[(size_t)B_ * T_ * D_];

// ---------------------------------------------------------------------------
// fast exp via exp2 polynomial (keeps the 67M exps off the MUFU pipe)
// ---------------------------------------------------------------------------
__device__ __forceinline__ float fast_exp(float x) {
    float t = x * 1.4426950408889634f;
    t = fmaxf(t, -126.0f);
    float fi = floorf(t);
    float f = t - fi;
    float p = 1.8775767e-3f;
    p = fmaf(p, f, 8.9893397e-3f);
    p = fmaf(p, f, 5.5826318e-2f);
    p = fmaf(p, f, 2.4015361e-1f);
    p = fmaf(p, f, 6.9315308e-1f);
    p = fmaf(p, f, 1.0f);
    return p * __int_as_float(((int)fi + 127) << 23);
}

// ---------------------------------------------------------------------------
// GEMM: C[m,n] = sum_k A[m,k] * W[n,k]  (i.e. A @ W^T), D_=512 deep.
// Tile 128x128, BK=16, 256 threads, 8x8 per thread.
// mode 0: Q  -> g_Q2 (+bias +pos_bias_u / pos_bias_v, split layout)
// mode 1: K  -> g_K (+bias)
// mode 2: V  -> g_V (+bias)
// mode 3: P  -> g_P (no bias), M=1024
// mode 4: O  -> Cout plain (+bias), A = g_ctx
// ---------------------------------------------------------------------------
__global__ __launch_bounds__(256) void gemm512(
    const float* __restrict__ A, const float* __restrict__ W,
    const float* __restrict__ bias,
    const float* __restrict__ ubias, const float* __restrict__ vbias,
    float* __restrict__ Cout, int mode)
{
    __shared__ float As[16 * 128];
    __shared__ float Bs[16 * 128];

    const float* Ap = (mode == 4) ? g_ctx : A;

    int tid = threadIdx.x;
    int m0 = blockIdx.y * 128;
    int n0 = blockIdx.x * 128;
    int tm = tid >> 4;      // 0..15
    int tn = tid & 15;      // 0..15

    int r  = tid >> 1;          // 0..127 (load row)
    int cq = (tid & 1) * 8;     // 0 or 8 (load col group)

    float acc[8][8];
    #pragma unroll
    for (int i = 0; i < 8; i++)
        #pragma unroll
        for (int j = 0; j < 8; j++) acc[i][j] = 0.f;

    for (int k0 = 0; k0 < D_; k0 += 16) {
        // Load A tile (transposed into As[k][m]) and W tile (Bs[k][n])
        float4 a0 = *(const float4*)(Ap + (size_t)(m0 + r) * D_ + k0 + cq);
        float4 a1 = *(const float4*)(Ap + (size_t)(m0 + r) * D_ + k0 + cq + 4);
        float4 b0 = *(const float4*)(W  + (size_t)(n0 + r) * D_ + k0 + cq);
        float4 b1 = *(const float4*)(W  + (size_t)(n0 + r) * D_ + k0 + cq + 4);
        As[(cq + 0) * 128 + r] = a0.x; As[(cq + 1) * 128 + r] = a0.y;
        As[(cq + 2) * 128 + r] = a0.z; As[(cq + 3) * 128 + r] = a0.w;
        As[(cq + 4) * 128 + r] = a1.x; As[(cq + 5) * 128 + r] = a1.y;
        As[(cq + 6) * 128 + r] = a1.z; As[(cq + 7) * 128 + r] = a1.w;
        Bs[(cq + 0) * 128 + r] = b0.x; Bs[(cq + 1) * 128 + r] = b0.y;
        Bs[(cq + 2) * 128 + r] = b0.z; Bs[(cq + 3) * 128 + r] = b0.w;
        Bs[(cq + 4) * 128 + r] = b1.x; Bs[(cq + 5) * 128 + r] = b1.y;
        Bs[(cq + 6) * 128 + r] = b1.z; Bs[(cq + 7) * 128 + r] = b1.w;
        __syncthreads();

        #pragma unroll
        for (int kk = 0; kk < 16; kk++) {
            float a[8], b[8];
            *(float4*)&a[0] = *(float4*)&As[kk * 128 + tm * 8];
            *(float4*)&a[4] = *(float4*)&As[kk * 128 + tm * 8 + 4];
            *(float4*)&b[0] = *(float4*)&Bs[kk * 128 + tn * 8];
            *(float4*)&b[4] = *(float4*)&Bs[kk * 128 + tn * 8 + 4];
            #pragma unroll
            for (int i = 0; i < 8; i++)
                #pragma unroll
                for (int j = 0; j < 8; j++)
                    acc[i][j] = fmaf(a[i], b[j], acc[i][j]);
        }
        __syncthreads();
    }

    // Epilogue
    #pragma unroll
    for (int i = 0; i < 8; i++) {
        int m = m0 + tm * 8 + i;
        int b = m >> 10;          // m / 1024
        int t = m & 1023;
        #pragma unroll
        for (int j = 0; j < 8; j++) {
            int n  = n0 + tn * 8 + j;
            int h  = n >> 6;
            int dk = n & 63;
            float v = acc[i][j];
            if (mode == 0) {
                v += bias[n];
                size_t base = ((size_t)(b * H_ + h) * T_ + t) * 128 + dk;
                g_Q2[base]      = v + ubias[n];
                g_Q2[base + 64] = v + vbias[n];
            } else if (mode == 1) {
                g_K[((size_t)(b * H_ + h) * T_ + t) * DK_ + dk] = v + bias[n];
            } else if (mode == 2) {
                g_V[((size_t)(b * H_ + h) * T_ + t) * DK_ + dk] = v + bias[n];
            } else if (mode == 3) {
                g_P[((size_t)h * T_ + m) * DK_ + dk] = v;   // M=1024 -> m == t
            } else {
                Cout[(size_t)m * D_ + n] = v + bias[n];
            }
        }
    }
}

// ---------------------------------------------------------------------------
// Flash attention with rel-pos:  s = ((q+u)·k + (q+v)·p) / 8, key mask,
// online softmax, ctx = attn @ V.  BM=BN=64, 256 threads, 4x4 per thread.
// ---------------------------------------------------------------------------
#define PAD 68
#define ATTN_SMEM ((128*PAD + 64*PAD + 64*PAD + 64*64 + 64*PAD + 64*3) * 4 + 64 * 4)

__global__ __launch_bounds__(256) void attn_kernel(const int* __restrict__ mask)
{
    extern __shared__ float sh[];
    float* Qs    = sh;                   // [128][PAD]  (d-major, q inner)
    float* Ks    = Qs + 128 * PAD;       // [64][PAD]
    float* Ps    = Ks + 64 * PAD;        // [64][PAD]
    float* Vs    = Ps + 64 * PAD;        // [64][64]   (k-major, d inner)
    float* Ss    = Vs + 64 * 64;         // [64][PAD]  (k-major, q inner)
    float* sm_m  = Ss + 64 * PAD;
    float* sm_l  = sm_m + 64;
    float* sm_sc = sm_l + 64;
    int*   sm_mk = (int*)(sm_sc + 64);

    int tid = threadIdx.x;
    int bh  = blockIdx.y;
    int b   = bh >> 3;
    int h   = bh & 7;
    int q0  = blockIdx.x * 64;
    int tq  = tid >> 4;   // 0..15
    int tk  = tid & 15;   // 0..15

    // load Q2 tile (64 rows x 128) transposed into Qs[d][q]
    const float* Qg = g_Q2 + ((size_t)bh * T_ + q0) * 128;
    #pragma unroll
    for (int i = 0; i < 8; i++) {
        int lin = tid + i * 256;       // float4 index, 2048 total
        int q   = lin >> 5;
        int dg  = lin & 31;
        float4 a = *(const float4*)(Qg + q * 128 + dg * 4);
        Qs[(dg * 4 + 0) * PAD + q] = a.x;
        Qs[(dg * 4 + 1) * PAD + q] = a.y;
        Qs[(dg * 4 + 2) * PAD + q] = a.z;
        Qs[(dg * 4 + 3) * PAD + q] = a.w;
    }
    if (tid < 64) { sm_m[tid] = -1e30f; sm_l[tid] = 0.f; }

    float o[4][4];
    #pragma unroll
    for (int i = 0; i < 4; i++)
        #pragma unroll
        for (int j = 0; j < 4; j++) o[i][j] = 0.f;

    const float* Kg = g_K + (size_t)bh * T_ * DK_;
    const float* Pg = g_P + (size_t)h  * T_ * DK_;
    const float* Vg = g_V + (size_t)bh * T_ * DK_;
    const int*   mg = mask + b * T_;

    __syncthreads();

    for (int k0 = 0; k0 < T_; k0 += 64) {
        // load K,P (transposed) and V (natural) tiles
        #pragma unroll
        for (int i = 0; i < 4; i++) {
            int lin = tid + i * 256;   // float4 index, 1024 total
            int k   = lin >> 4;
            int dg  = lin & 15;
            float4 a = *(const float4*)(Kg + (size_t)(k0 + k) * DK_ + dg * 4);
            Ks[(dg * 4 + 0) * PAD + k] = a.x;
            Ks[(dg * 4 + 1) * PAD + k] = a.y;
            Ks[(dg * 4 + 2) * PAD + k] = a.z;
            Ks[(dg * 4 + 3) * PAD + k] = a.w;
            float4 p = *(const float4*)(Pg + (size_t)(k0 + k) * DK_ + dg * 4);
            Ps[(dg * 4 + 0) * PAD + k] = p.x;
            Ps[(dg * 4 + 1) * PAD + k] = p.y;
            Ps[(dg * 4 + 2) * PAD + k] = p.z;
            Ps[(dg * 4 + 3) * PAD + k] = p.w;
            float4 vv = *(const float4*)(Vg + (size_t)(k0 + k) * DK_ + dg * 4);
            *(float4*)(Vs + k * 64 + dg * 4) = vv;
        }
        if (tid < 64) sm_mk[tid] = mg[k0 + tid];
        __syncthreads();

        // scores: s[i][j] = sum_d Qu[q][d]*K[k][d] + Qv[q][d]*P[k][d]
        float s[4][4];
        #pragma unroll
        for (int i = 0; i < 4; i++)
            #pragma unroll
            for (int j = 0; j < 4; j++) s[i][j] = 0.f;

        #pragma unroll 4
        for (int d = 0; d < 64; d++) {
            float qu[4], qv[4], kf[4], pf[4];
            *(float4*)qu = *(float4*)(Qs + d * PAD + tq * 4);
            *(float4*)qv = *(float4*)(Qs + (64 + d) * PAD + tq * 4);
            *(float4*)kf = *(float4*)(Ks + d * PAD + tk * 4);
            *(float4*)pf = *(float4*)(Ps + d * PAD + tk * 4);
            #pragma unroll
            for (int i = 0; i < 4; i++)
                #pragma unroll
                for (int j = 0; j < 4; j++) {
                    s[i][j] = fmaf(qu[i], kf[j], s[i][j]);
                    s[i][j] = fmaf(qv[i], pf[j], s[i][j]);
                }
        }

        // scale + mask
        int km[4];
        #pragma unroll
        for (int j = 0; j < 4; j++) km[j] = sm_mk[tk * 4 + j];
        float rmax[4];
        #pragma unroll
        for (int i = 0; i < 4; i++) {
            #pragma unroll
            for (int j = 0; j < 4; j++)
                s[i][j] = km[j] ? s[i][j] * 0.125f : -1e30f;
            rmax[i] = fmaxf(fmaxf(s[i][0], s[i][1]), fmaxf(s[i][2], s[i][3]));
        }
        // reduce row max over the 16 lanes of this q-group
        #pragma unroll
        for (int off = 8; off >= 1; off >>= 1)
            #pragma unroll
            for (int i = 0; i < 4; i++)
                rmax[i] = fmaxf(rmax[i], __shfl_xor_sync(0xffffffffu, rmax[i], off));

        float mnew[4], sc[4], rsum[4];
        #pragma unroll
        for (int i = 0; i < 4; i++) {
            int row = tq * 4 + i;
            float mo = sm_m[row];
            mnew[i]  = fmaxf(mo, rmax[i]);
            sc[i]    = fast_exp(mo - mnew[i]);
            rsum[i]  = 0.f;
        }
        #pragma unroll
        for (int i = 0; i < 4; i++)
            #pragma unroll
            for (int j = 0; j < 4; j++) {
                float p = fast_exp(s[i][j] - mnew[i]);
                s[i][j] = p;
                rsum[i] += p;
            }
        #pragma unroll
        for (int off = 8; off >= 1; off >>= 1)
            #pragma unroll
            for (int i = 0; i < 4; i++)
                rsum[i] += __shfl_xor_sync(0xffffffffu, rsum[i], off);

        if (tk == 0) {
            #pragma unroll
            for (int i = 0; i < 4; i++) {
                int row = tq * 4 + i;
                sm_m[row]  = mnew[i];
                sm_l[row]  = sm_l[row] * sc[i] + rsum[i];
                sm_sc[row] = sc[i];
            }
        }
        // store probabilities transposed: Ss[k][q]
        #pragma unroll
        for (int i = 0; i < 4; i++)
            #pragma unroll
            for (int j = 0; j < 4; j++)
                Ss[(tk * 4 + j) * PAD + tq * 4 + i] = s[i][j];
        __syncthreads();

        // rescale o, accumulate P @ V  (thread now covers q-group tq, d-group tk)
        float scl[4];
        #pragma unroll
        for (int i = 0; i < 4; i++) scl[i] = sm_sc[tq * 4 + i];
        #pragma unroll
        for (int i = 0; i < 4; i++)
            #pragma unroll
            for (int j = 0; j < 4; j++) o[i][j] *= scl[i];

        #pragma unroll 4
        for (int k = 0; k < 64; k++) {
            float sf[4], vf[4];
            *(float4*)sf = *(float4*)(Ss + k * PAD + tq * 4);
            *(float4*)vf = *(float4*)(Vs + k * 64 + tk * 4);
            #pragma unroll
            for (int i = 0; i < 4; i++)
                #pragma unroll
                for (int j = 0; j < 4; j++)
                    o[i][j] = fmaf(sf[i], vf[j], o[i][j]);
        }
        __syncthreads();
    }

    // epilogue: divide by row sums, write ctx[b, t, h*64+dk]
    #pragma unroll
    for (int i = 0; i < 4; i++) {
        float l  = sm_l[tq * 4 + i];
        float rl = (l > 0.f) ? (1.f / l) : 0.f;
        int t    = q0 + tq * 4 + i;
        float4 w;
        w.x = o[i][0] * rl; w.y = o[i][1] * rl;
        w.z = o[i][2] * rl; w.w = o[i][3] * rl;
        *(float4*)(g_ctx + ((size_t)b * T_ + t) * D_ + h * 64 + tk * 4) = w;
    }
}

// ---------------------------------------------------------------------------
extern "C" void kernel_launch(void* const* d_in, const int* in_sizes, int n_in,
                              void* d_out, int out_size)
{
    (void)in_sizes; (void)n_in; (void)out_size;
    const float* query   = (const float*)d_in[0];
    const float* key_    = (const float*)d_in[1];
    const float* value   = (const float*)d_in[2];
    const int*   mask    = (const int*)  d_in[3];
    const float* pos_emb = (const float*)d_in[4];
    const float* Wq      = (const float*)d_in[5];
    const float* bq      = (const float*)d_in[6];
    const float* Wk      = (const float*)d_in[7];
    const float* bk      = (const float*)d_in[8];
    const float* Wv      = (const float*)d_in[9];
    const float* bv      = (const float*)d_in[10];
    const float* Wp      = (const float*)d_in[11];
    const float* Wo      = (const float*)d_in[12];
    const float* bo      = (const float*)d_in[13];
    const float* pbu     = (const float*)d_in[14];
    const float* pbv     = (const float*)d_in[15];

    cudaFuncSetAttribute(attn_kernel,
                         cudaFuncAttributeMaxDynamicSharedMemorySize, ATTN_SMEM);

    gemm512<<<dim3(4, 64), 256>>>(query,   Wq, bq, pbu, pbv, nullptr, 0);
    gemm512<<<dim3(4, 64), 256>>>(key_,    Wk, bk, nullptr, nullptr, nullptr, 1);
    gemm512<<<dim3(4, 64), 256>>>(value,   Wv, bv, nullptr, nullptr, nullptr, 2);
    gemm512<<<dim3(4, 8),  256>>>(pos_emb, Wp, nullptr, nullptr, nullptr, nullptr, 3);
    attn_kernel<<<dim3(16, 64), 256, ATTN_SMEM>>>(mask);
    gemm512<<<dim3(4, 64), 256>>>(nullptr, Wo, bo, nullptr, nullptr, (float*)d_out, 4);
}

// round 6
// speedup vs baseline: 2.7456x; 2.7456x over previous
#include <cuda_runtime.h>
#include <cuda_bf16.h>
#include <cstdint>

#define B_ 8
#define T_ 1024
#define D_ 512
#define H_ 8
#define DK_ 64
#define BH_ (B_ * H_)

// ---------------------------------------------------------------------------
// Static scratch (no allocation allowed). bf16 hi/lo pre-split operands.
// ---------------------------------------------------------------------------
__device__ __nv_bfloat16 g_Q2h[(size_t)BH_ * T_ * 128];  // [bh][t][0:64]=q+u hi, [64:128]=q+v hi
__device__ __nv_bfloat16 g_Q2l[(size_t)BH_ * T_ * 128];
__device__ __nv_bfloat16 g_Kh[(size_t)BH_ * T_ * DK_];
__device__ __nv_bfloat16 g_Kl[(size_t)BH_ * T_ * DK_];
__device__ __nv_bfloat16 g_Vh[(size_t)BH_ * T_ * DK_];
__device__ __nv_bfloat16 g_Vl[(size_t)BH_ * T_ * DK_];
__device__ __nv_bfloat16 g_Ph[(size_t)H_ * T_ * DK_];
__device__ __nv_bfloat16 g_Pl[(size_t)H_ * T_ * DK_];
__device__ float g_ctx[(size_t)B_ * T_ * D_];

// ---------------------------------------------------------------------------
// Helpers
// ---------------------------------------------------------------------------
__device__ __forceinline__ uint32_t smem_u32(const void* p) {
    uint32_t a;
    asm("{ .reg .u64 t; cvta.to.shared.u64 t, %1; cvt.u32.u64 %0, t; }"
        : "=r"(a) : "l"(p));
    return a;
}

__device__ __forceinline__ void ldm_x4(uint32_t* r, uint32_t addr) {
    asm volatile("ldmatrix.sync.aligned.m8n8.x4.shared.b16 {%0,%1,%2,%3}, [%4];"
                 : "=r"(r[0]), "=r"(r[1]), "=r"(r[2]), "=r"(r[3]) : "r"(addr));
}
__device__ __forceinline__ void ldm_x4_t(uint32_t* r, uint32_t addr) {
    asm volatile("ldmatrix.sync.aligned.m8n8.x4.trans.shared.b16 {%0,%1,%2,%3}, [%4];"
                 : "=r"(r[0]), "=r"(r[1]), "=r"(r[2]), "=r"(r[3]) : "r"(addr));
}
// D(16x8,f32) += A(16x16,bf16) * B(16x8,bf16)
__device__ __forceinline__ void mma_bf16(float* d, const uint32_t* a,
                                         uint32_t b0, uint32_t b1) {
    asm volatile(
        "mma.sync.aligned.m16n8k16.row.col.f32.bf16.bf16.f32 "
        "{%0,%1,%2,%3}, {%4,%5,%6,%7}, {%8,%9}, {%0,%1,%2,%3};"
        : "+f"(d[0]), "+f"(d[1]), "+f"(d[2]), "+f"(d[3])
        : "r"(a[0]), "r"(a[1]), "r"(a[2]), "r"(a[3]), "r"(b0), "r"(b1));
}

// split fp32 pair -> packed bf16 hi (truncated) + bf16 lo (rn of residual)
__device__ __forceinline__ void split_pack(float x0, float x1,
                                           uint32_t& hi, uint32_t& lo) {
    uint32_t u0 = __float_as_uint(x0), u1 = __float_as_uint(x1);
    hi = __byte_perm(u0, u1, 0x7632);          // low16 = u0>>16, high16 = u1>>16
    float h0 = __uint_as_float(u0 & 0xFFFF0000u);
    float h1 = __uint_as_float(u1 & 0xFFFF0000u);
    __nv_bfloat162 p = __floats2bfloat162_rn(x0 - h0, x1 - h1);
    lo = *(uint32_t*)&p;
}

__device__ __forceinline__ float fast_exp(float x) {
    float t = x * 1.4426950408889634f;
    t = fmaxf(t, -126.0f);
    float fi = floorf(t);
    float f = t - fi;
    float p = 1.8775767e-3f;
    p = fmaf(p, f, 8.9893397e-3f);
    p = fmaf(p, f, 5.5826318e-2f);
    p = fmaf(p, f, 2.4015361e-1f);
    p = fmaf(p, f, 6.9315308e-1f);
    p = fmaf(p, f, 1.0f);
    return p * __int_as_float(((int)fi + 127) << 23);
}

// ---------------------------------------------------------------------------
// mma.sync split-bf16 GEMM: C[m,n] = sum_k A[m,k] * W[n,k], K=512.
// 128x128 tile, K-chunk 64, 256 threads (8 warps, 4m x 2n, warp tile 32x64).
// mode 0: Q -> g_Q2h/l (+bias+u/v), 1: K, 2: V, 3: P, 4: O -> Cout fp32
// ---------------------------------------------------------------------------
#define GS_ROWB 144                    // 72 halves per row (64 data + 8 pad)
#define GS_BYTES (128 * GS_ROWB)       // 18432 per tile
#define SOFF_AHI 0
#define SOFF_ALO (GS_BYTES)
#define SOFF_WHI (2 * GS_BYTES)
#define SOFF_WLO (3 * GS_BYTES)
#define GEMM_SMEM (4 * GS_BYTES)       // 73728
#define CS_STRIDE 132

__global__ __launch_bounds__(256) void gemm_tc(
    const float* __restrict__ A, const float* __restrict__ W,
    const float* __restrict__ bias,
    const float* __restrict__ ubias, const float* __restrict__ vbias,
    float* __restrict__ Cout, int mode)
{
    extern __shared__ char smem[];
    uint32_t sb = smem_u32(smem);
    int tid = threadIdx.x;
    int w = tid >> 5, l = tid & 31;
    int wm = w >> 1, wn = w & 1;
    int gid = l >> 2, tig = l & 3;
    int m0 = blockIdx.y * 128, n0 = blockIdx.x * 128;

    const float* Ap = (mode == 4) ? g_ctx : A;

    float acc[2][8][4];
    #pragma unroll
    for (int i = 0; i < 2; i++)
        #pragma unroll
        for (int j = 0; j < 8; j++)
            #pragma unroll
            for (int c = 0; c < 4; c++) acc[i][j][c] = 0.f;

    for (int ch = 0; ch < 8; ch++) {
        int k0 = ch * 64;
        // Load 128x64 fp32 of A and W; split to bf16 hi/lo in padded smem.
        #pragma unroll
        for (int i = 0; i < 8; i++) {
            int idx = tid + i * 256;        // 2048 float4 per matrix
            int row = idx >> 4;
            int c4  = idx & 15;
            uint32_t dst = row * GS_ROWB + c4 * 8;
            float4 a = *(const float4*)(Ap + (size_t)(m0 + row) * D_ + k0 + c4 * 4);
            uint32_t h0, l0, h1, l1;
            split_pack(a.x, a.y, h0, l0);
            split_pack(a.z, a.w, h1, l1);
            *(uint2*)(smem + SOFF_AHI + dst) = make_uint2(h0, h1);
            *(uint2*)(smem + SOFF_ALO + dst) = make_uint2(l0, l1);
            float4 wv = *(const float4*)(W + (size_t)(n0 + row) * D_ + k0 + c4 * 4);
            split_pack(wv.x, wv.y, h0, l0);
            split_pack(wv.z, wv.w, h1, l1);
            *(uint2*)(smem + SOFF_WHI + dst) = make_uint2(h0, h1);
            *(uint2*)(smem + SOFF_WLO + dst) = make_uint2(l0, l1);
        }
        __syncthreads();

        #pragma unroll
        for (int ks = 0; ks < 4; ks++) {
            uint32_t ah[2][4], al2[2][4];
            {
                int arow = wm * 32 + ((l >> 3) & 1) * 8 + (l & 7);
                int kc = ks * 16 + ((l >> 4) << 3);
                uint32_t off = arow * GS_ROWB + kc * 2;
                ldm_x4(ah[0], sb + SOFF_AHI + off);
                ldm_x4(ah[1], sb + SOFF_AHI + off + 16 * GS_ROWB);
                ldm_x4(al2[0], sb + SOFF_ALO + off);
                ldm_x4(al2[1], sb + SOFF_ALO + off + 16 * GS_ROWB);
            }
            #pragma unroll
            for (int nt = 0; nt < 4; nt++) {
                int nrow = wn * 64 + nt * 16 + ((l >> 4) << 3) + (l & 7);
                int kc = ks * 16 + (((l >> 3) & 1) << 3);
                uint32_t boff = nrow * GS_ROWB + kc * 2;
                uint32_t bh[4], bl2[4];
                ldm_x4(bh, sb + SOFF_WHI + boff);
                ldm_x4(bl2, sb + SOFF_WLO + boff);
                #pragma unroll
                for (int mt = 0; mt < 2; mt++) {
                    mma_bf16(acc[mt][nt * 2],     ah[mt],  bh[0],  bh[1]);
                    mma_bf16(acc[mt][nt * 2],     ah[mt],  bl2[0], bl2[1]);
                    mma_bf16(acc[mt][nt * 2],     al2[mt], bh[0],  bh[1]);
                    mma_bf16(acc[mt][nt * 2 + 1], ah[mt],  bh[2],  bh[3]);
                    mma_bf16(acc[mt][nt * 2 + 1], ah[mt],  bl2[2], bl2[3]);
                    mma_bf16(acc[mt][nt * 2 + 1], al2[mt], bh[2],  bh[3]);
                }
            }
        }
        __syncthreads();
    }

    // Phase 1: fragments -> smem staging (fp32, padded)
    float* Cs = (float*)smem;
    #pragma unroll
    for (int mt = 0; mt < 2; mt++)
        #pragma unroll
        for (int nt8 = 0; nt8 < 8; nt8++) {
            int ml = wm * 32 + mt * 16 + gid;
            int nl = wn * 64 + nt8 * 8 + tig * 2;
            *(float2*)&Cs[ml * CS_STRIDE + nl] =
                make_float2(acc[mt][nt8][0], acc[mt][nt8][1]);
            *(float2*)&Cs[(ml + 8) * CS_STRIDE + nl] =
                make_float2(acc[mt][nt8][2], acc[mt][nt8][3]);
        }
    __syncthreads();

    // Phase 2: smem -> gmem, coalesced; emit bf16 hi/lo splits for modes 0-3.
    #pragma unroll
    for (int i = 0; i < 16; i++) {
        int idx = tid + i * 256;            // 4096 float4
        int ml = idx >> 5;
        int nl = (idx & 31) * 4;
        float4 v = *(float4*)&Cs[ml * CS_STRIDE + nl];
        int m = m0 + ml, n = n0 + nl;
        int b = m >> 10, t = m & 1023;
        int h = n >> 6, dk = n & 63;
        if (mode == 0) {
            float4 bb = *(const float4*)(bias + n);
            float4 uu = *(const float4*)(ubias + n);
            float4 vv = *(const float4*)(vbias + n);
            float q0f = v.x + bb.x, q1f = v.y + bb.y, q2f = v.z + bb.z, q3f = v.w + bb.w;
            size_t base = ((size_t)(b * H_ + h) * T_ + t) * 128 + dk;
            uint32_t h0, l0, h1, l1;
            split_pack(q0f + uu.x, q1f + uu.y, h0, l0);
            split_pack(q2f + uu.z, q3f + uu.w, h1, l1);
            *(uint2*)(g_Q2h + base) = make_uint2(h0, h1);
            *(uint2*)(g_Q2l + base) = make_uint2(l0, l1);
            split_pack(q0f + vv.x, q1f + vv.y, h0, l0);
            split_pack(q2f + vv.z, q3f + vv.w, h1, l1);
            *(uint2*)(g_Q2h + base + 64) = make_uint2(h0, h1);
            *(uint2*)(g_Q2l + base + 64) = make_uint2(l0, l1);
        } else if (mode == 1 || mode == 2) {
            float4 bb = *(const float4*)(bias + n);
            float x0 = v.x + bb.x, x1 = v.y + bb.y, x2 = v.z + bb.z, x3 = v.w + bb.w;
            size_t base = ((size_t)(b * H_ + h) * T_ + t) * DK_ + dk;
            uint32_t h0, l0, h1, l1;
            split_pack(x0, x1, h0, l0);
            split_pack(x2, x3, h1, l1);
            if (mode == 1) {
                *(uint2*)(g_Kh + base) = make_uint2(h0, h1);
                *(uint2*)(g_Kl + base) = make_uint2(l0, l1);
            } else {
                *(uint2*)(g_Vh + base) = make_uint2(h0, h1);
                *(uint2*)(g_Vl + base) = make_uint2(l0, l1);
            }
        } else if (mode == 3) {
            size_t base = ((size_t)h * T_ + m) * DK_ + dk;   // M=1024 -> m == t
            uint32_t h0, l0, h1, l1;
            split_pack(v.x, v.y, h0, l0);
            split_pack(v.z, v.w, h1, l1);
            *(uint2*)(g_Ph + base) = make_uint2(h0, h1);
            *(uint2*)(g_Pl + base) = make_uint2(l0, l1);
        } else {
            float4 bb = *(const float4*)(bias + n);
            v.x += bb.x; v.y += bb.y; v.z += bb.z; v.w += bb.w;
            *(float4*)(Cout + (size_t)m * D_ + n) = v;
        }
    }
}

// ---------------------------------------------------------------------------
// Flash attention, mma.sync split-bf16.
// s = ((q+u)*K^T + (q+v)*P^T)/8 + mask_bias; online softmax; O = P@V.
// Block: 128 threads (4 warps, 16 q-rows each), BM=64, BN=64, 16 kt-tiles.
// ---------------------------------------------------------------------------
#define Q_ROWB 272                      // 136 halves (128 data + 8 pad)
#define K_ROWB 144                      // 72 halves (64 data + 8 pad)
#define AOFF_QH 0
#define AOFF_QL (64 * Q_ROWB)           // 17408
#define AOFF_KH (2 * 64 * Q_ROWB)       // 34816
#define AOFF_KL (AOFF_KH + 64 * K_ROWB)
#define AOFF_PH (AOFF_KL + 64 * K_ROWB)
#define AOFF_PL (AOFF_PH + 64 * K_ROWB)
#define AOFF_VH (AOFF_PL + 64 * K_ROWB)
#define AOFF_VL (AOFF_VH + 64 * K_ROWB)
#define AOFF_BIAS (AOFF_VL + 64 * K_ROWB)   // 90112
#define ATTN_SMEM (AOFF_BIAS + 64 * 4)      // 90368

__global__ __launch_bounds__(128) void attn_kernel(const int* __restrict__ mask)
{
    extern __shared__ char smem[];
    uint32_t sb = smem_u32(smem);
    int tid = threadIdx.x;
    int w = tid >> 5, l = tid & 31;
    int gid = l >> 2, tig = l & 3;
    int bh = blockIdx.y;
    int b = bh >> 3, h = bh & 7;
    int q0 = blockIdx.x * 64;

    // Load Q2 hi/lo tile: 64 rows x 128 halves each
    {
        const __nv_bfloat16* qh = g_Q2h + ((size_t)bh * T_ + q0) * 128;
        const __nv_bfloat16* ql = g_Q2l + ((size_t)bh * T_ + q0) * 128;
        #pragma unroll
        for (int i = 0; i < 8; i++) {
            int lin = tid + i * 128;       // 1024 uint4 per array
            int row = lin >> 4, u = lin & 15;
            uint32_t dst = row * Q_ROWB + u * 16;
            *(uint4*)(smem + AOFF_QH + dst) = *(const uint4*)(qh + row * 128 + u * 8);
            *(uint4*)(smem + AOFF_QL + dst) = *(const uint4*)(ql + row * 128 + u * 8);
        }
    }
    __syncthreads();

    // Preload Q fragments for all 4 d-ksteps (hoisted across kt-tiles)
    uint32_t quh[4][4], qul[4][4], qvh[4][4], qvl[4][4];
    {
        int arow = w * 16 + ((l >> 3) & 1) * 8 + (l & 7);
        int kcb = ((l >> 4) << 3);
        #pragma unroll
        for (int ks = 0; ks < 4; ks++) {
            uint32_t offu = arow * Q_ROWB + (ks * 16 + kcb) * 2;
            uint32_t offv = arow * Q_ROWB + (64 + ks * 16 + kcb) * 2;
            ldm_x4(quh[ks], sb + AOFF_QH + offu);
            ldm_x4(qul[ks], sb + AOFF_QL + offu);
            ldm_x4(qvh[ks], sb + AOFF_QH + offv);
            ldm_x4(qvl[ks], sb + AOFF_QL + offv);
        }
    }

    float o[8][4];
    #pragma unroll
    for (int i = 0; i < 8; i++)
        #pragma unroll
        for (int c = 0; c < 4; c++) o[i][c] = 0.f;
    float row_m0 = -1e30f, row_m1 = -1e30f, row_l0 = 0.f, row_l1 = 0.f;

    const __nv_bfloat16* Kh = g_Kh + (size_t)bh * T_ * DK_;
    const __nv_bfloat16* Kl = g_Kl + (size_t)bh * T_ * DK_;
    const __nv_bfloat16* Vh = g_Vh + (size_t)bh * T_ * DK_;
    const __nv_bfloat16* Vl = g_Vl + (size_t)bh * T_ * DK_;
    const __nv_bfloat16* Ph = g_Ph + (size_t)h * T_ * DK_;
    const __nv_bfloat16* Pl = g_Pl + (size_t)h * T_ * DK_;
    const int* mg = mask + b * T_;
    float* sBias = (float*)(smem + AOFF_BIAS);

    for (int k0 = 0; k0 < T_; k0 += 64) {
        __syncthreads();
        // Load K/P/V hi/lo tiles (64 x 64 halves each) + mask bias
        #pragma unroll
        for (int i = 0; i < 4; i++) {
            int lin = tid + i * 128;       // 512 uint4 per array
            int row = lin >> 3, u = lin & 7;
            size_t src = (size_t)(k0 + row) * DK_ + u * 8;
            uint32_t dst = row * K_ROWB + u * 16;
            *(uint4*)(smem + AOFF_KH + dst) = *(const uint4*)(Kh + src);
            *(uint4*)(smem + AOFF_KL + dst) = *(const uint4*)(Kl + src);
            *(uint4*)(smem + AOFF_PH + dst) = *(const uint4*)(Ph + src);
            *(uint4*)(smem + AOFF_PL + dst) = *(const uint4*)(Pl + src);
            *(uint4*)(smem + AOFF_VH + dst) = *(const uint4*)(Vh + src);
            *(uint4*)(smem + AOFF_VL + dst) = *(const uint4*)(Vl + src);
        }
        if (tid < 64) sBias[tid] = mg[k0 + tid] ? 0.f : -1e30f;
        __syncthreads();

        // Scores: S(16q x 64kt) per warp
        float s[8][4];
        #pragma unroll
        for (int i = 0; i < 8; i++)
            #pragma unroll
            for (int c = 0; c < 4; c++) s[i][c] = 0.f;

        #pragma unroll
        for (int ks = 0; ks < 4; ks++) {
            #pragma unroll
            for (int nt = 0; nt < 4; nt++) {
                int nrow = nt * 16 + ((l >> 4) << 3) + (l & 7);
                uint32_t boff = nrow * K_ROWB + (ks * 16 + (((l >> 3) & 1) << 3)) * 2;
                uint32_t kbh[4], kbl[4], pbh[4], pbl[4];
                ldm_x4(kbh, sb + AOFF_KH + boff);
                ldm_x4(kbl, sb + AOFF_KL + boff);
                ldm_x4(pbh, sb + AOFF_PH + boff);
                ldm_x4(pbl, sb + AOFF_PL + boff);
                mma_bf16(s[nt * 2],     quh[ks], kbh[0], kbh[1]);
                mma_bf16(s[nt * 2],     quh[ks], kbl[0], kbl[1]);
                mma_bf16(s[nt * 2],     qul[ks], kbh[0], kbh[1]);
                mma_bf16(s[nt * 2],     qvh[ks], pbh[0], pbh[1]);
                mma_bf16(s[nt * 2],     qvh[ks], pbl[0], pbl[1]);
                mma_bf16(s[nt * 2],     qvl[ks], pbh[0], pbh[1]);
                mma_bf16(s[nt * 2 + 1], quh[ks], kbh[2], kbh[3]);
                mma_bf16(s[nt * 2 + 1], quh[ks], kbl[2], kbl[3]);
                mma_bf16(s[nt * 2 + 1], qul[ks], kbh[2], kbh[3]);
                mma_bf16(s[nt * 2 + 1], qvh[ks], pbh[2], pbh[3]);
                mma_bf16(s[nt * 2 + 1], qvh[ks], pbl[2], pbl[3]);
                mma_bf16(s[nt * 2 + 1], qvl[ks], pbh[2], pbh[3]);
            }
        }

        // scale + mask bias, row max (rows gid and gid+8 of this warp's m16)
        float rmax0 = -1e30f, rmax1 = -1e30f;
        #pragma unroll
        for (int nt8 = 0; nt8 < 8; nt8++) {
            int n = nt8 * 8 + tig * 2;
            float b0v = sBias[n], b1v = sBias[n + 1];
            s[nt8][0] = fmaf(s[nt8][0], 0.125f, b0v);
            s[nt8][1] = fmaf(s[nt8][1], 0.125f, b1v);
            s[nt8][2] = fmaf(s[nt8][2], 0.125f, b0v);
            s[nt8][3] = fmaf(s[nt8][3], 0.125f, b1v);
            rmax0 = fmaxf(rmax0, fmaxf(s[nt8][0], s[nt8][1]));
            rmax1 = fmaxf(rmax1, fmaxf(s[nt8][2], s[nt8][3]));
        }
        rmax0 = fmaxf(rmax0, __shfl_xor_sync(0xffffffffu, rmax0, 1));
        rmax0 = fmaxf(rmax0, __shfl_xor_sync(0xffffffffu, rmax0, 2));
        rmax1 = fmaxf(rmax1, __shfl_xor_sync(0xffffffffu, rmax1, 1));
        rmax1 = fmaxf(rmax1, __shfl_xor_sync(0xffffffffu, rmax1, 2));

        float mn0 = fmaxf(row_m0, rmax0), mn1 = fmaxf(row_m1, rmax1);
        float sc0 = fast_exp(row_m0 - mn0), sc1 = fast_exp(row_m1 - mn1);
        float rs0 = 0.f, rs1 = 0.f;
        #pragma unroll
        for (int nt8 = 0; nt8 < 8; nt8++) {
            s[nt8][0] = fast_exp(s[nt8][0] - mn0); rs0 += s[nt8][0];
            s[nt8][1] = fast_exp(s[nt8][1] - mn0); rs0 += s[nt8][1];
            s[nt8][2] = fast_exp(s[nt8][2] - mn1); rs1 += s[nt8][2];
            s[nt8][3] = fast_exp(s[nt8][3] - mn1); rs1 += s[nt8][3];
        }
        rs0 += __shfl_xor_sync(0xffffffffu, rs0, 1);
        rs0 += __shfl_xor_sync(0xffffffffu, rs0, 2);
        rs1 += __shfl_xor_sync(0xffffffffu, rs1, 1);
        rs1 += __shfl_xor_sync(0xffffffffu, rs1, 2);
        row_l0 = row_l0 * sc0 + rs0;
        row_l1 = row_l1 * sc1 + rs1;
        row_m0 = mn0; row_m1 = mn1;

        #pragma unroll
        for (int dt = 0; dt < 8; dt++) {
            o[dt][0] *= sc0; o[dt][1] *= sc0;
            o[dt][2] *= sc1; o[dt][3] *= sc1;
        }

        // probs -> A fragments (hi/lo) for PV; S regs feed A directly
        uint32_t pah[4][4], pal[4][4];
        #pragma unroll
        for (int ks = 0; ks < 4; ks++) {
            split_pack(s[2 * ks][0],     s[2 * ks][1],     pah[ks][0], pal[ks][0]);
            split_pack(s[2 * ks][2],     s[2 * ks][3],     pah[ks][1], pal[ks][1]);
            split_pack(s[2 * ks + 1][0], s[2 * ks + 1][1], pah[ks][2], pal[ks][2]);
            split_pack(s[2 * ks + 1][2], s[2 * ks + 1][3], pah[ks][3], pal[ks][3]);
        }

        // O += P @ V  (V via ldmatrix.trans)
        #pragma unroll
        for (int ks = 0; ks < 4; ks++) {
            int ktrow = ks * 16 + ((l >> 3) & 1) * 8 + (l & 7);
            int dcb = ((l >> 4) << 3);
            #pragma unroll
            for (int dt2 = 0; dt2 < 4; dt2++) {
                uint32_t voff = ktrow * K_ROWB + (dt2 * 16 + dcb) * 2;
                uint32_t vbh[4], vbl[4];
                ldm_x4_t(vbh, sb + AOFF_VH + voff);
                ldm_x4_t(vbl, sb + AOFF_VL + voff);
                mma_bf16(o[dt2 * 2],     pah[ks], vbh[0], vbh[1]);
                mma_bf16(o[dt2 * 2],     pah[ks], vbl[0], vbl[1]);
                mma_bf16(o[dt2 * 2],     pal[ks], vbh[0], vbh[1]);
                mma_bf16(o[dt2 * 2 + 1], pah[ks], vbh[2], vbh[3]);
                mma_bf16(o[dt2 * 2 + 1], pah[ks], vbl[2], vbl[3]);
                mma_bf16(o[dt2 * 2 + 1], pal[ks], vbh[2], vbh[3]);
            }
        }
    }

    // Epilogue: divide by row sums; write ctx[b, t, h*64+d]
    float rl0 = (row_l0 > 0.f) ? (1.f / row_l0) : 0.f;
    float rl1 = (row_l1 > 0.f) ? (1.f / row_l1) : 0.f;
    int t0 = q0 + w * 16 + gid;
    int t1 = t0 + 8;
    #pragma unroll
    for (int dt = 0; dt < 8; dt++) {
        int d = dt * 8 + tig * 2;
        *(float2*)(g_ctx + ((size_t)b * T_ + t0) * D_ + h * 64 + d) =
            make_float2(o[dt][0] * rl0, o[dt][1] * rl0);
        *(float2*)(g_ctx + ((size_t)b * T_ + t1) * D_ + h * 64 + d) =
            make_float2(o[dt][2] * rl1, o[dt][3] * rl1);
    }
}

// ---------------------------------------------------------------------------
extern "C" void kernel_launch(void* const* d_in, const int* in_sizes, int n_in,
                              void* d_out, int out_size)
{
    (void)in_sizes; (void)n_in; (void)out_size;
    const float* query   = (const float*)d_in[0];
    const float* key_    = (const float*)d_in[1];
    const float* value   = (const float*)d_in[2];
    const int*   mask    = (const int*)  d_in[3];
    const float* pos_emb = (const float*)d_in[4];
    const float* Wq      = (const float*)d_in[5];
    const float* bq      = (const float*)d_in[6];
    const float* Wk      = (const float*)d_in[7];
    const float* bk      = (const float*)d_in[8];
    const float* Wv      = (const float*)d_in[9];
    const float* bv      = (const float*)d_in[10];
    const float* Wp      = (const float*)d_in[11];
    const float* Wo      = (const float*)d_in[12];
    const float* bo      = (const float*)d_in[13];
    const float* pbu     = (const float*)d_in[14];
    const float* pbv     = (const float*)d_in[15];

    cudaFuncSetAttribute(gemm_tc,
                         cudaFuncAttributeMaxDynamicSharedMemorySize, GEMM_SMEM);
    cudaFuncSetAttribute(attn_kernel,
                         cudaFuncAttributeMaxDynamicSharedMemorySize, ATTN_SMEM);

    gemm_tc<<<dim3(4, 64), 256, GEMM_SMEM>>>(query,   Wq, bq, pbu, pbv, nullptr, 0);
    gemm_tc<<<dim3(4, 64), 256, GEMM_SMEM>>>(key_,    Wk, bk, nullptr, nullptr, nullptr, 1);
    gemm_tc<<<dim3(4, 64), 256, GEMM_SMEM>>>(value,   Wv, bv, nullptr, nullptr, nullptr, 2);
    gemm_tc<<<dim3(4, 8),  256, GEMM_SMEM>>>(pos_emb, Wp, nullptr, nullptr, nullptr, nullptr, 3);
    attn_kernel<<<dim3(16, 64), 128, ATTN_SMEM>>>(mask);
    gemm_tc<<<dim3(4, 64), 256, GEMM_SMEM>>>(nullptr, Wo, bo, nullptr, nullptr, (float*)d_out, 4);
}

// round 7
// speedup vs baseline: 2.7546x; 1.0033x over previous
#include <cuda_runtime.h>
#include <cuda_bf16.h>
#include <cstdint>

#define B_ 8
#define T_ 1024
#define D_ 512
#define H_ 8
#define DK_ 64
#define BH_ (B_ * H_)

// ---------------------------------------------------------------------------
// Static scratch (no allocation allowed). bf16 hi/lo pre-split operands.
// ---------------------------------------------------------------------------
__device__ __nv_bfloat16 g_Q2h[(size_t)BH_ * T_ * 128];  // [bh][t][0:64]=q+u hi, [64:128]=q+v hi
__device__ __nv_bfloat16 g_Q2l[(size_t)BH_ * T_ * 128];
__device__ __nv_bfloat16 g_Kh[(size_t)BH_ * T_ * DK_];
__device__ __nv_bfloat16 g_Kl[(size_t)BH_ * T_ * DK_];
__device__ __nv_bfloat16 g_Vh[(size_t)BH_ * T_ * DK_];
__device__ __nv_bfloat16 g_Vl[(size_t)BH_ * T_ * DK_];
__device__ __nv_bfloat16 g_Ph[(size_t)H_ * T_ * DK_];
__device__ __nv_bfloat16 g_Pl[(size_t)H_ * T_ * DK_];
__device__ float g_ctx[(size_t)B_ * T_ * D_];

// ---------------------------------------------------------------------------
// Helpers
// ---------------------------------------------------------------------------
__device__ __forceinline__ uint32_t smem_u32(const void* p) {
    uint32_t a;
    asm("{ .reg .u64 t; cvta.to.shared.u64 t, %1; cvt.u32.u64 %0, t; }"
        : "=r"(a) : "l"(p));
    return a;
}

__device__ __forceinline__ void ldm_x4(uint32_t* r, uint32_t addr) {
    asm volatile("ldmatrix.sync.aligned.m8n8.x4.shared.b16 {%0,%1,%2,%3}, [%4];"
                 : "=r"(r[0]), "=r"(r[1]), "=r"(r[2]), "=r"(r[3]) : "r"(addr));
}
__device__ __forceinline__ void ldm_x4_t(uint32_t* r, uint32_t addr) {
    asm volatile("ldmatrix.sync.aligned.m8n8.x4.trans.shared.b16 {%0,%1,%2,%3}, [%4];"
                 : "=r"(r[0]), "=r"(r[1]), "=r"(r[2]), "=r"(r[3]) : "r"(addr));
}
// D(16x8,f32) += A(16x16,bf16) * B(16x8,bf16)
__device__ __forceinline__ void mma_bf16(float* d, const uint32_t* a,
                                         uint32_t b0, uint32_t b1) {
    asm volatile(
        "mma.sync.aligned.m16n8k16.row.col.f32.bf16.bf16.f32 "
        "{%0,%1,%2,%3}, {%4,%5,%6,%7}, {%8,%9}, {%0,%1,%2,%3};"
        : "+f"(d[0]), "+f"(d[1]), "+f"(d[2]), "+f"(d[3])
        : "r"(a[0]), "r"(a[1]), "r"(a[2]), "r"(a[3]), "r"(b0), "r"(b1));
}

// split fp32 pair -> packed bf16 hi (truncated) + bf16 lo (rn of residual)
__device__ __forceinline__ void split_pack(float x0, float x1,
                                           uint32_t& hi, uint32_t& lo) {
    uint32_t u0 = __float_as_uint(x0), u1 = __float_as_uint(x1);
    hi = __byte_perm(u0, u1, 0x7632);          // low16 = u0>>16, high16 = u1>>16
    float h0 = __uint_as_float(u0 & 0xFFFF0000u);
    float h1 = __uint_as_float(u1 & 0xFFFF0000u);
    __nv_bfloat162 p = __floats2bfloat162_rn(x0 - h0, x1 - h1);
    lo = *(uint32_t*)&p;
}

__device__ __forceinline__ float fast_exp(float x) {
    float t = x * 1.4426950408889634f;
    t = fmaxf(t, -126.0f);
    float fi = floorf(t);
    float f = t - fi;
    float p = 1.8775767e-3f;
    p = fmaf(p, f, 8.9893397e-3f);
    p = fmaf(p, f, 5.5826318e-2f);
    p = fmaf(p, f, 2.4015361e-1f);
    p = fmaf(p, f, 6.9315308e-1f);
    p = fmaf(p, f, 1.0f);
    return p * __int_as_float(((int)fi + 127) << 23);
}

// ---------------------------------------------------------------------------
// mma.sync split-bf16 GEMM: C[m,n] = sum_k A[m,k] * W[n,k], K=512.
// 128x128 tile, K-chunk 64, 256 threads (8 warps, 4m x 2n, warp tile 32x64).
// mode 0: Q -> g_Q2h/l (+bias+u/v), 1: K, 2: V, 3: P, 4: O -> Cout fp32
// ---------------------------------------------------------------------------
#define GS_ROWB 144                    // 72 halves per row (64 data + 8 pad)
#define GS_BYTES (128 * GS_ROWB)       // 18432 per tile
#define SOFF_AHI 0
#define SOFF_ALO (GS_BYTES)
#define SOFF_WHI (2 * GS_BYTES)
#define SOFF_WLO (3 * GS_BYTES)
#define GEMM_SMEM (4 * GS_BYTES)       // 73728
#define CS_STRIDE 132

__global__ __launch_bounds__(256) void gemm_tc(
    const float* __restrict__ A, const float* __restrict__ W,
    const float* __restrict__ bias,
    const float* __restrict__ ubias, const float* __restrict__ vbias,
    float* __restrict__ Cout, int mode)
{
    extern __shared__ char smem[];
    uint32_t sb = smem_u32(smem);
    int tid = threadIdx.x;
    int w = tid >> 5, l = tid & 31;
    int wm = w >> 1, wn = w & 1;
    int gid = l >> 2, tig = l & 3;
    int m0 = blockIdx.y * 128, n0 = blockIdx.x * 128;

    const float* Ap = (mode == 4) ? g_ctx : A;

    float acc[2][8][4];
    #pragma unroll
    for (int i = 0; i < 2; i++)
        #pragma unroll
        for (int j = 0; j < 8; j++)
            #pragma unroll
            for (int c = 0; c < 4; c++) acc[i][j][c] = 0.f;

    for (int ch = 0; ch < 8; ch++) {
        int k0 = ch * 64;
        // Load 128x64 fp32 of A and W; split to bf16 hi/lo in padded smem.
        #pragma unroll
        for (int i = 0; i < 8; i++) {
            int idx = tid + i * 256;        // 2048 float4 per matrix
            int row = idx >> 4;
            int c4  = idx & 15;
            uint32_t dst = row * GS_ROWB + c4 * 8;
            float4 a = *(const float4*)(Ap + (size_t)(m0 + row) * D_ + k0 + c4 * 4);
            uint32_t h0, l0, h1, l1;
            split_pack(a.x, a.y, h0, l0);
            split_pack(a.z, a.w, h1, l1);
            *(uint2*)(smem + SOFF_AHI + dst) = make_uint2(h0, h1);
            *(uint2*)(smem + SOFF_ALO + dst) = make_uint2(l0, l1);
            float4 wv = *(const float4*)(W + (size_t)(n0 + row) * D_ + k0 + c4 * 4);
            split_pack(wv.x, wv.y, h0, l0);
            split_pack(wv.z, wv.w, h1, l1);
            *(uint2*)(smem + SOFF_WHI + dst) = make_uint2(h0, h1);
            *(uint2*)(smem + SOFF_WLO + dst) = make_uint2(l0, l1);
        }
        __syncthreads();

        #pragma unroll
        for (int ks = 0; ks < 4; ks++) {
            uint32_t ah[2][4], al2[2][4];
            {
                int arow = wm * 32 + ((l >> 3) & 1) * 8 + (l & 7);
                int kc = ks * 16 + ((l >> 4) << 3);
                uint32_t off = arow * GS_ROWB + kc * 2;
                ldm_x4(ah[0], sb + SOFF_AHI + off);
                ldm_x4(ah[1], sb + SOFF_AHI + off + 16 * GS_ROWB);
                ldm_x4(al2[0], sb + SOFF_ALO + off);
                ldm_x4(al2[1], sb + SOFF_ALO + off + 16 * GS_ROWB);
            }
            #pragma unroll
            for (int nt = 0; nt < 4; nt++) {
                int nrow = wn * 64 + nt * 16 + ((l >> 4) << 3) + (l & 7);
                int kc = ks * 16 + (((l >> 3) & 1) << 3);
                uint32_t boff = nrow * GS_ROWB + kc * 2;
                uint32_t bh[4], bl2[4];
                ldm_x4(bh, sb + SOFF_WHI + boff);
                ldm_x4(bl2, sb + SOFF_WLO + boff);
                #pragma unroll
                for (int mt = 0; mt < 2; mt++) {
                    mma_bf16(acc[mt][nt * 2],     ah[mt],  bh[0],  bh[1]);
                    mma_bf16(acc[mt][nt * 2],     ah[mt],  bl2[0], bl2[1]);
                    mma_bf16(acc[mt][nt * 2],     al2[mt], bh[0],  bh[1]);
                    mma_bf16(acc[mt][nt * 2 + 1], ah[mt],  bh[2],  bh[3]);
                    mma_bf16(acc[mt][nt * 2 + 1], ah[mt],  bl2[2], bl2[3]);
                    mma_bf16(acc[mt][nt * 2 + 1], al2[mt], bh[2],  bh[3]);
                }
            }
        }
        __syncthreads();
    }

    // Phase 1: fragments -> smem staging (fp32, padded)
    float* Cs = (float*)smem;
    #pragma unroll
    for (int mt = 0; mt < 2; mt++)
        #pragma unroll
        for (int nt8 = 0; nt8 < 8; nt8++) {
            int ml = wm * 32 + mt * 16 + gid;
            int nl = wn * 64 + nt8 * 8 + tig * 2;
            *(float2*)&Cs[ml * CS_STRIDE + nl] =
                make_float2(acc[mt][nt8][0], acc[mt][nt8][1]);
            *(float2*)&Cs[(ml + 8) * CS_STRIDE + nl] =
                make_float2(acc[mt][nt8][2], acc[mt][nt8][3]);
        }
    __syncthreads();

    // Phase 2: smem -> gmem, coalesced; emit bf16 hi/lo splits for modes 0-3.
    #pragma unroll
    for (int i = 0; i < 16; i++) {
        int idx = tid + i * 256;            // 4096 float4
        int ml = idx >> 5;
        int nl = (idx & 31) * 4;
        float4 v = *(float4*)&Cs[ml * CS_STRIDE + nl];
        int m = m0 + ml, n = n0 + nl;
        int b = m >> 10, t = m & 1023;
        int h = n >> 6, dk = n & 63;
        if (mode == 0) {
            float4 bb = *(const float4*)(bias + n);
            float4 uu = *(const float4*)(ubias + n);
            float4 vv = *(const float4*)(vbias + n);
            float q0f = v.x + bb.x, q1f = v.y + bb.y, q2f = v.z + bb.z, q3f = v.w + bb.w;
            size_t base = ((size_t)(b * H_ + h) * T_ + t) * 128 + dk;
            uint32_t h0, l0, h1, l1;
            split_pack(q0f + uu.x, q1f + uu.y, h0, l0);
            split_pack(q2f + uu.z, q3f + uu.w, h1, l1);
            *(uint2*)(g_Q2h + base) = make_uint2(h0, h1);
            *(uint2*)(g_Q2l + base) = make_uint2(l0, l1);
            split_pack(q0f + vv.x, q1f + vv.y, h0, l0);
            split_pack(q2f + vv.z, q3f + vv.w, h1, l1);
            *(uint2*)(g_Q2h + base + 64) = make_uint2(h0, h1);
            *(uint2*)(g_Q2l + base + 64) = make_uint2(l0, l1);
        } else if (mode == 1 || mode == 2) {
            float4 bb = *(const float4*)(bias + n);
            float x0 = v.x + bb.x, x1 = v.y + bb.y, x2 = v.z + bb.z, x3 = v.w + bb.w;
            size_t base = ((size_t)(b * H_ + h) * T_ + t) * DK_ + dk;
            uint32_t h0, l0, h1, l1;
            split_pack(x0, x1, h0, l0);
            split_pack(x2, x3, h1, l1);
            if (mode == 1) {
                *(uint2*)(g_Kh + base) = make_uint2(h0, h1);
                *(uint2*)(g_Kl + base) = make_uint2(l0, l1);
            } else {
                *(uint2*)(g_Vh + base) = make_uint2(h0, h1);
                *(uint2*)(g_Vl + base) = make_uint2(l0, l1);
            }
        } else if (mode == 3) {
            size_t base = ((size_t)h * T_ + m) * DK_ + dk;   // M=1024 -> m == t
            uint32_t h0, l0, h1, l1;
            split_pack(v.x, v.y, h0, l0);
            split_pack(v.z, v.w, h1, l1);
            *(uint2*)(g_Ph + base) = make_uint2(h0, h1);
            *(uint2*)(g_Pl + base) = make_uint2(l0, l1);
        } else {
            float4 bb = *(const float4*)(bias + n);
            v.x += bb.x; v.y += bb.y; v.z += bb.z; v.w += bb.w;
            *(float4*)(Cout + (size_t)m * D_ + n) = v;
        }
    }
}

// ---------------------------------------------------------------------------
// Flash attention, mma.sync split-bf16.
// s = ((q+u)*K^T + (q+v)*P^T)/8 + mask_bias; online softmax; O = P@V.
// Block: 128 threads (4 warps, 16 q-rows each), BM=64, BN=64, 16 kt-tiles.
// ---------------------------------------------------------------------------
#define Q_ROWB 272                      // 136 halves (128 data + 8 pad)
#define K_ROWB 144                      // 72 halves (64 data + 8 pad)
#define AOFF_QH 0
#define AOFF_QL (64 * Q_ROWB)           // 17408
#define AOFF_KH (2 * 64 * Q_ROWB)       // 34816
#define AOFF_KL (AOFF_KH + 64 * K_ROWB)
#define AOFF_PH (AOFF_KL + 64 * K_ROWB)
#define AOFF_PL (AOFF_PH + 64 * K_ROWB)
#define AOFF_VH (AOFF_PL + 64 * K_ROWB)
#define AOFF_VL (AOFF_VH + 64 * K_ROWB)
#define AOFF_BIAS (AOFF_VL + 64 * K_ROWB)   // 90112
#define ATTN_SMEM (AOFF_BIAS + 64 * 4)      // 90368

__global__ __launch_bounds__(128) void attn_kernel(const int* __restrict__ mask)
{
    extern __shared__ char smem[];
    uint32_t sb = smem_u32(smem);
    int tid = threadIdx.x;
    int w = tid >> 5, l = tid & 31;
    int gid = l >> 2, tig = l & 3;
    int bh = blockIdx.y;
    int b = bh >> 3, h = bh & 7;
    int q0 = blockIdx.x * 64;

    // Load Q2 hi/lo tile: 64 rows x 128 halves each
    {
        const __nv_bfloat16* qh = g_Q2h + ((size_t)bh * T_ + q0) * 128;
        const __nv_bfloat16* ql = g_Q2l + ((size_t)bh * T_ + q0) * 128;
        #pragma unroll
        for (int i = 0; i < 8; i++) {
            int lin = tid + i * 128;       // 1024 uint4 per array
            int row = lin >> 4, u = lin & 15;
            uint32_t dst = row * Q_ROWB + u * 16;
            *(uint4*)(smem + AOFF_QH + dst) = *(const uint4*)(qh + row * 128 + u * 8);
            *(uint4*)(smem + AOFF_QL + dst) = *(const uint4*)(ql + row * 128 + u * 8);
        }
    }
    __syncthreads();

    // Preload Q fragments for all 4 d-ksteps (hoisted across kt-tiles)
    uint32_t quh[4][4], qul[4][4], qvh[4][4], qvl[4][4];
    {
        int arow = w * 16 + ((l >> 3) & 1) * 8 + (l & 7);
        int kcb = ((l >> 4) << 3);
        #pragma unroll
        for (int ks = 0; ks < 4; ks++) {
            uint32_t offu = arow * Q_ROWB + (ks * 16 + kcb) * 2;
            uint32_t offv = arow * Q_ROWB + (64 + ks * 16 + kcb) * 2;
            ldm_x4(quh[ks], sb + AOFF_QH + offu);
            ldm_x4(qul[ks], sb + AOFF_QL + offu);
            ldm_x4(qvh[ks], sb + AOFF_QH + offv);
            ldm_x4(qvl[ks], sb + AOFF_QL + offv);
        }
    }

    float o[8][4];
    #pragma unroll
    for (int i = 0; i < 8; i++)
        #pragma unroll
        for (int c = 0; c < 4; c++) o[i][c] = 0.f;
    float row_m0 = -1e30f, row_m1 = -1e30f, row_l0 = 0.f, row_l1 = 0.f;

    const __nv_bfloat16* Kh = g_Kh + (size_t)bh * T_ * DK_;
    const __nv_bfloat16* Kl = g_Kl + (size_t)bh * T_ * DK_;
    const __nv_bfloat16* Vh = g_Vh + (size_t)bh * T_ * DK_;
    const __nv_bfloat16* Vl = g_Vl + (size_t)bh * T_ * DK_;
    const __nv_bfloat16* Ph = g_Ph + (size_t)h * T_ * DK_;
    const __nv_bfloat16* Pl = g_Pl + (size_t)h * T_ * DK_;
    const int* mg = mask + b * T_;
    float* sBias = (float*)(smem + AOFF_BIAS);

    for (int k0 = 0; k0 < T_; k0 += 64) {
        __syncthreads();
        // Load K/P/V hi/lo tiles (64 x 64 halves each) + mask bias
        #pragma unroll
        for (int i = 0; i < 4; i++) {
            int lin = tid + i * 128;       // 512 uint4 per array
            int row = lin >> 3, u = lin & 7;
            size_t src = (size_t)(k0 + row) * DK_ + u * 8;
            uint32_t dst = row * K_ROWB + u * 16;
            *(uint4*)(smem + AOFF_KH + dst) = *(const uint4*)(Kh + src);
            *(uint4*)(smem + AOFF_KL + dst) = *(const uint4*)(Kl + src);
            *(uint4*)(smem + AOFF_PH + dst) = *(const uint4*)(Ph + src);
            *(uint4*)(smem + AOFF_PL + dst) = *(const uint4*)(Pl + src);
            *(uint4*)(smem + AOFF_VH + dst) = *(const uint4*)(Vh + src);
            *(uint4*)(smem + AOFF_VL + dst) = *(const uint4*)(Vl + src);
        }
        if (tid < 64) sBias[tid] = mg[k0 + tid] ? 0.f : -1e30f;
        __syncthreads();

        // Scores: S(16q x 64kt) per warp
        float s[8][4];
        #pragma unroll
        for (int i = 0; i < 8; i++)
            #pragma unroll
            for (int c = 0; c < 4; c++) s[i][c] = 0.f;

        #pragma unroll
        for (int ks = 0; ks < 4; ks++) {
            #pragma unroll
            for (int nt = 0; nt < 4; nt++) {
                int nrow = nt * 16 + ((l >> 4) << 3) + (l & 7);
                uint32_t boff = nrow * K_ROWB + (ks * 16 + (((l >> 3) & 1) << 3)) * 2;
                uint32_t kbh[4], kbl[4], pbh[4], pbl[4];
                ldm_x4(kbh, sb + AOFF_KH + boff);
                ldm_x4(kbl, sb + AOFF_KL + boff);
                ldm_x4(pbh, sb + AOFF_PH + boff);
                ldm_x4(pbl, sb + AOFF_PL + boff);
                mma_bf16(s[nt * 2],     quh[ks], kbh[0], kbh[1]);
                mma_bf16(s[nt * 2],     quh[ks], kbl[0], kbl[1]);
                mma_bf16(s[nt * 2],     qul[ks], kbh[0], kbh[1]);
                mma_bf16(s[nt * 2],     qvh[ks], pbh[0], pbh[1]);
                mma_bf16(s[nt * 2],     qvh[ks], pbl[0], pbl[1]);
                mma_bf16(s[nt * 2],     qvl[ks], pbh[0], pbh[1]);
                mma_bf16(s[nt * 2 + 1], quh[ks], kbh[2], kbh[3]);
                mma_bf16(s[nt * 2 + 1], quh[ks], kbl[2], kbl[3]);
                mma_bf16(s[nt * 2 + 1], qul[ks], kbh[2], kbh[3]);
                mma_bf16(s[nt * 2 + 1], qvh[ks], pbh[2], pbh[3]);
                mma_bf16(s[nt * 2 + 1], qvh[ks], pbl[2], pbl[3]);
                mma_bf16(s[nt * 2 + 1], qvl[ks], pbh[2], pbh[3]);
            }
        }

        // scale + mask bias, row max (rows gid and gid+8 of this warp's m16)
        float rmax0 = -1e30f, rmax1 = -1e30f;
        #pragma unroll
        for (int nt8 = 0; nt8 < 8; nt8++) {
            int n = nt8 * 8 + tig * 2;
            float b0v = sBias[n], b1v = sBias[n + 1];
            s[nt8][0] = fmaf(s[nt8][0], 0.125f, b0v);
            s[nt8][1] = fmaf(s[nt8][1], 0.125f, b1v);
            s[nt8][2] = fmaf(s[nt8][2], 0.125f, b0v);
            s[nt8][3] = fmaf(s[nt8][3], 0.125f, b1v);
            rmax0 = fmaxf(rmax0, fmaxf(s[nt8][0], s[nt8][1]));
            rmax1 = fmaxf(rmax1, fmaxf(s[nt8][2], s[nt8][3]));
        }
        rmax0 = fmaxf(rmax0, __shfl_xor_sync(0xffffffffu, rmax0, 1));
        rmax0 = fmaxf(rmax0, __shfl_xor_sync(0xffffffffu, rmax0, 2));
        rmax1 = fmaxf(rmax1, __shfl_xor_sync(0xffffffffu, rmax1, 1));
        rmax1 = fmaxf(rmax1, __shfl_xor_sync(0xffffffffu, rmax1, 2));

        float mn0 = fmaxf(row_m0, rmax0), mn1 = fmaxf(row_m1, rmax1);
        float sc0 = fast_exp(row_m0 - mn0), sc1 = fast_exp(row_m1 - mn1);
        float rs0 = 0.f, rs1 = 0.f;
        #pragma unroll
        for (int nt8 = 0; nt8 < 8; nt8++) {
            s[nt8][0] = fast_exp(s[nt8][0] - mn0); rs0 += s[nt8][0];
            s[nt8][1] = fast_exp(s[nt8][1] - mn0); rs0 += s[nt8][1];
            s[nt8][2] = fast_exp(s[nt8][2] - mn1); rs1 += s[nt8][2];
            s[nt8][3] = fast_exp(s[nt8][3] - mn1); rs1 += s[nt8][3];
        }
        rs0 += __shfl_xor_sync(0xffffffffu, rs0, 1);
        rs0 += __shfl_xor_sync(0xffffffffu, rs0, 2);
        rs1 += __shfl_xor_sync(0xffffffffu, rs1, 1);
        rs1 += __shfl_xor_sync(0xffffffffu, rs1, 2);
        row_l0 = row_l0 * sc0 + rs0;
        row_l1 = row_l1 * sc1 + rs1;
        row_m0 = mn0; row_m1 = mn1;

        #pragma unroll
        for (int dt = 0; dt < 8; dt++) {
            o[dt][0] *= sc0; o[dt][1] *= sc0;
            o[dt][2] *= sc1; o[dt][3] *= sc1;
        }

        // probs -> A fragments (hi/lo) for PV; S regs feed A directly
        uint32_t pah[4][4], pal[4][4];
        #pragma unroll
        for (int ks = 0; ks < 4; ks++) {
            split_pack(s[2 * ks][0],     s[2 * ks][1],     pah[ks][0], pal[ks][0]);
            split_pack(s[2 * ks][2],     s[2 * ks][3],     pah[ks][1], pal[ks][1]);
            split_pack(s[2 * ks + 1][0], s[2 * ks + 1][1], pah[ks][2], pal[ks][2]);
            split_pack(s[2 * ks + 1][2], s[2 * ks + 1][3], pah[ks][3], pal[ks][3]);
        }

        // O += P @ V  (V via ldmatrix.trans)
        #pragma unroll
        for (int ks = 0; ks < 4; ks++) {
            int ktrow = ks * 16 + ((l >> 3) & 1) * 8 + (l & 7);
            int dcb = ((l >> 4) << 3);
            #pragma unroll
            for (int dt2 = 0; dt2 < 4; dt2++) {
                uint32_t voff = ktrow * K_ROWB + (dt2 * 16 + dcb) * 2;
                uint32_t vbh[4], vbl[4];
                ldm_x4_t(vbh, sb + AOFF_VH + voff);
                ldm_x4_t(vbl, sb + AOFF_VL + voff);
                mma_bf16(o[dt2 * 2],     pah[ks], vbh[0], vbh[1]);
                mma_bf16(o[dt2 * 2],     pah[ks], vbl[0], vbl[1]);
                mma_bf16(o[dt2 * 2],     pal[ks], vbh[0], vbh[1]);
                mma_bf16(o[dt2 * 2 + 1], pah[ks], vbh[2], vbh[3]);
                mma_bf16(o[dt2 * 2 + 1], pah[ks], vbl[2], vbl[3]);
                mma_bf16(o[dt2 * 2 + 1], pal[ks], vbh[2], vbh[3]);
            }
        }
    }

    // Epilogue: divide by row sums; write ctx[b, t, h*64+d]
    float rl0 = (row_l0 > 0.f) ? (1.f / row_l0) : 0.f;
    float rl1 = (row_l1 > 0.f) ? (1.f / row_l1) : 0.f;
    int t0 = q0 + w * 16 + gid;
    int t1 = t0 + 8;
    #pragma unroll
    for (int dt = 0; dt < 8; dt++) {
        int d = dt * 8 + tig * 2;
        *(float2*)(g_ctx + ((size_t)b * T_ + t0) * D_ + h * 64 + d) =
            make_float2(o[dt][0] * rl0, o[dt][1] * rl0);
        *(float2*)(g_ctx + ((size_t)b * T_ + t1) * D_ + h * 64 + d) =
            make_float2(o[dt][2] * rl1, o[dt][3] * rl1);
    }
}

// ---------------------------------------------------------------------------
extern "C" void kernel_launch(void* const* d_in, const int* in_sizes, int n_in,
                              void* d_out, int out_size)
{
    (void)in_sizes; (void)n_in; (void)out_size;
    const float* query   = (const float*)d_in[0];
    const float* key_    = (const float*)d_in[1];
    const float* value   = (const float*)d_in[2];
    const int*   mask    = (const int*)  d_in[3];
    const float* pos_emb = (const float*)d_in[4];
    const float* Wq      = (const float*)d_in[5];
    const float* bq      = (const float*)d_in[6];
    const float* Wk      = (const float*)d_in[7];
    const float* bk      = (const float*)d_in[8];
    const float* Wv      = (const float*)d_in[9];
    const float* bv      = (const float*)d_in[10];
    const float* Wp      = (const float*)d_in[11];
    const float* Wo      = (const float*)d_in[12];
    const float* bo      = (const float*)d_in[13];
    const float* pbu     = (const float*)d_in[14];
    const float* pbv     = (const float*)d_in[15];

    cudaFuncSetAttribute(gemm_tc,
                         cudaFuncAttributeMaxDynamicSharedMemorySize, GEMM_SMEM);
    cudaFuncSetAttribute(attn_kernel,
                         cudaFuncAttributeMaxDynamicSharedMemorySize, ATTN_SMEM);

    gemm_tc<<<dim3(4, 64), 256, GEMM_SMEM>>>(query,   Wq, bq, pbu, pbv, nullptr, 0);
    gemm_tc<<<dim3(4, 64), 256, GEMM_SMEM>>>(key_,    Wk, bk, nullptr, nullptr, nullptr, 1);
    gemm_tc<<<dim3(4, 64), 256, GEMM_SMEM>>>(value,   Wv, bv, nullptr, nullptr, nullptr, 2);
    gemm_tc<<<dim3(4, 8),  256, GEMM_SMEM>>>(pos_emb, Wp, nullptr, nullptr, nullptr, nullptr, 3);
    attn_kernel<<<dim3(16, 64), 128, ATTN_SMEM>>>(mask);
    gemm_tc<<<dim3(4, 64), 256, GEMM_SMEM>>>(nullptr, Wo, bo, nullptr, nullptr, (float*)d_out, 4);
}

// round 8
// speedup vs baseline: 3.4837x; 1.2647x over previous
#include <cuda_runtime.h>
#include <cuda_bf16.h>
#include <cstdint>

#define B_ 8
#define T_ 1024
#define D_ 512
#define H_ 8
#define DK_ 64
#define BH_ (B_ * H_)

// ---------------------------------------------------------------------------
// Static scratch (no allocation allowed). bf16 hi/lo pre-split operands.
// ---------------------------------------------------------------------------
__device__ __nv_bfloat16 g_Q2h[(size_t)BH_ * T_ * 128];  // [bh][t][0:64]=q+u hi, [64:128]=q+v hi
__device__ __nv_bfloat16 g_Q2l[(size_t)BH_ * T_ * 128];
__device__ __nv_bfloat16 g_Kh[(size_t)BH_ * T_ * DK_];
__device__ __nv_bfloat16 g_Kl[(size_t)BH_ * T_ * DK_];
__device__ __nv_bfloat16 g_Vh[(size_t)BH_ * T_ * DK_];
__device__ __nv_bfloat16 g_Vl[(size_t)BH_ * T_ * DK_];
__device__ __nv_bfloat16 g_Ph[(size_t)H_ * T_ * DK_];
__device__ __nv_bfloat16 g_Pl[(size_t)H_ * T_ * DK_];
__device__ float g_ctx[(size_t)B_ * T_ * D_];

// ---------------------------------------------------------------------------
// Helpers
// ---------------------------------------------------------------------------
__device__ __forceinline__ uint32_t smem_u32(const void* p) {
    uint32_t a;
    asm("{ .reg .u64 t; cvta.to.shared.u64 t, %1; cvt.u32.u64 %0, t; }"
        : "=r"(a) : "l"(p));
    return a;
}

__device__ __forceinline__ void ldm_x4(uint32_t* r, uint32_t addr) {
    asm volatile("ldmatrix.sync.aligned.m8n8.x4.shared.b16 {%0,%1,%2,%3}, [%4];"
                 : "=r"(r[0]), "=r"(r[1]), "=r"(r[2]), "=r"(r[3]) : "r"(addr));
}
__device__ __forceinline__ void ldm_x4_t(uint32_t* r, uint32_t addr) {
    asm volatile("ldmatrix.sync.aligned.m8n8.x4.trans.shared.b16 {%0,%1,%2,%3}, [%4];"
                 : "=r"(r[0]), "=r"(r[1]), "=r"(r[2]), "=r"(r[3]) : "r"(addr));
}
// D(16x8,f32) += A(16x16,bf16) * B(16x8,bf16)
__device__ __forceinline__ void mma_bf16(float* d, const uint32_t* a,
                                         uint32_t b0, uint32_t b1) {
    asm volatile(
        "mma.sync.aligned.m16n8k16.row.col.f32.bf16.bf16.f32 "
        "{%0,%1,%2,%3}, {%4,%5,%6,%7}, {%8,%9}, {%0,%1,%2,%3};"
        : "+f"(d[0]), "+f"(d[1]), "+f"(d[2]), "+f"(d[3])
        : "r"(a[0]), "r"(a[1]), "r"(a[2]), "r"(a[3]), "r"(b0), "r"(b1));
}

__device__ __forceinline__ void cp16(uint32_t dst, const void* src) {
    asm volatile("cp.async.cg.shared.global [%0], [%1], 16;"
                 :: "r"(dst), "l"(src) : "memory");
}
__device__ __forceinline__ void cp_wait_all() {
    asm volatile("cp.async.commit_group;" ::: "memory");
    asm volatile("cp.async.wait_group 0;" ::: "memory");
}

// split fp32 pair -> packed bf16 hi (truncated) + bf16 lo (rn of residual)
__device__ __forceinline__ void split_pack(float x0, float x1,
                                           uint32_t& hi, uint32_t& lo) {
    uint32_t u0 = __float_as_uint(x0), u1 = __float_as_uint(x1);
    hi = __byte_perm(u0, u1, 0x7632);          // low16 = u0>>16, high16 = u1>>16
    float h0 = __uint_as_float(u0 & 0xFFFF0000u);
    float h1 = __uint_as_float(u1 & 0xFFFF0000u);
    __nv_bfloat162 p = __floats2bfloat162_rn(x0 - h0, x1 - h1);
    lo = *(uint32_t*)&p;
}

__device__ __forceinline__ float fast_exp(float x) {
    float t = x * 1.4426950408889634f;
    t = fmaxf(t, -126.0f);
    float fi = floorf(t);
    float f = t - fi;
    float p = 1.8775767e-3f;
    p = fmaf(p, f, 8.9893397e-3f);
    p = fmaf(p, f, 5.5826318e-2f);
    p = fmaf(p, f, 2.4015361e-1f);
    p = fmaf(p, f, 6.9315308e-1f);
    p = fmaf(p, f, 1.0f);
    return p * __int_as_float(((int)fi + 127) << 23);
}

// ---------------------------------------------------------------------------
// mma.sync split-bf16 GEMM body: C[m,n] = sum_k A[m,k] * W[n,k], K=512.
// 128x128 tile, K-chunk 64, 256 threads (8 warps, 4m x 2n, warp tile 32x64).
// mode 0: Q -> g_Q2h/l (+bias+u/v), 1: K, 2: V, 3: P, 4: O -> Cout fp32
// ---------------------------------------------------------------------------
#define GS_ROWB 144                    // 72 halves per row (64 data + 8 pad)
#define GS_BYTES (128 * GS_ROWB)       // 18432 per tile
#define SOFF_AHI 0
#define SOFF_ALO (GS_BYTES)
#define SOFF_WHI (2 * GS_BYTES)
#define SOFF_WLO (3 * GS_BYTES)
#define GEMM_SMEM (4 * GS_BYTES)       // 73728
#define CS_STRIDE 132

__device__ __forceinline__ void gemm_body(
    char* smem, uint32_t sb,
    const float* __restrict__ Ap, const float* __restrict__ W,
    const float* __restrict__ bias,
    const float* __restrict__ ubias, const float* __restrict__ vbias,
    float* __restrict__ Cout, int mode, int m0, int n0)
{
    int tid = threadIdx.x;
    int w = tid >> 5, l = tid & 31;
    int wm = w >> 1, wn = w & 1;
    int gid = l >> 2, tig = l & 3;

    float acc[2][8][4];
    #pragma unroll
    for (int i = 0; i < 2; i++)
        #pragma unroll
        for (int j = 0; j < 8; j++)
            #pragma unroll
            for (int c = 0; c < 4; c++) acc[i][j][c] = 0.f;

    for (int ch = 0; ch < 8; ch++) {
        int k0 = ch * 64;
        // Load 128x64 fp32 of A and W; split to bf16 hi/lo in padded smem.
        #pragma unroll
        for (int i = 0; i < 8; i++) {
            int idx = tid + i * 256;        // 2048 float4 per matrix
            int row = idx >> 4;
            int c4  = idx & 15;
            uint32_t dst = row * GS_ROWB + c4 * 8;
            float4 a = *(const float4*)(Ap + (size_t)(m0 + row) * D_ + k0 + c4 * 4);
            uint32_t h0, l0, h1, l1;
            split_pack(a.x, a.y, h0, l0);
            split_pack(a.z, a.w, h1, l1);
            *(uint2*)(smem + SOFF_AHI + dst) = make_uint2(h0, h1);
            *(uint2*)(smem + SOFF_ALO + dst) = make_uint2(l0, l1);
            float4 wv = *(const float4*)(W + (size_t)(n0 + row) * D_ + k0 + c4 * 4);
            split_pack(wv.x, wv.y, h0, l0);
            split_pack(wv.z, wv.w, h1, l1);
            *(uint2*)(smem + SOFF_WHI + dst) = make_uint2(h0, h1);
            *(uint2*)(smem + SOFF_WLO + dst) = make_uint2(l0, l1);
        }
        __syncthreads();

        #pragma unroll
        for (int ks = 0; ks < 4; ks++) {
            uint32_t ah[2][4], al2[2][4];
            {
                int arow = wm * 32 + ((l >> 3) & 1) * 8 + (l & 7);
                int kc = ks * 16 + ((l >> 4) << 3);
                uint32_t off = arow * GS_ROWB + kc * 2;
                ldm_x4(ah[0], sb + SOFF_AHI + off);
                ldm_x4(ah[1], sb + SOFF_AHI + off + 16 * GS_ROWB);
                ldm_x4(al2[0], sb + SOFF_ALO + off);
                ldm_x4(al2[1], sb + SOFF_ALO + off + 16 * GS_ROWB);
            }
            #pragma unroll
            for (int nt = 0; nt < 4; nt++) {
                int nrow = wn * 64 + nt * 16 + ((l >> 4) << 3) + (l & 7);
                int kc = ks * 16 + (((l >> 3) & 1) << 3);
                uint32_t boff = nrow * GS_ROWB + kc * 2;
                uint32_t bh[4], bl2[4];
                ldm_x4(bh, sb + SOFF_WHI + boff);
                ldm_x4(bl2, sb + SOFF_WLO + boff);
                #pragma unroll
                for (int mt = 0; mt < 2; mt++) {
                    mma_bf16(acc[mt][nt * 2],     ah[mt],  bh[0],  bh[1]);
                    mma_bf16(acc[mt][nt * 2],     ah[mt],  bl2[0], bl2[1]);
                    mma_bf16(acc[mt][nt * 2],     al2[mt], bh[0],  bh[1]);
                    mma_bf16(acc[mt][nt * 2 + 1], ah[mt],  bh[2],  bh[3]);
                    mma_bf16(acc[mt][nt * 2 + 1], ah[mt],  bl2[2], bl2[3]);
                    mma_bf16(acc[mt][nt * 2 + 1], al2[mt], bh[2],  bh[3]);
                }
            }
        }
        __syncthreads();
    }

    // Phase 1: fragments -> smem staging (fp32, padded)
    float* Cs = (float*)smem;
    #pragma unroll
    for (int mt = 0; mt < 2; mt++)
        #pragma unroll
        for (int nt8 = 0; nt8 < 8; nt8++) {
            int ml = wm * 32 + mt * 16 + gid;
            int nl = wn * 64 + nt8 * 8 + tig * 2;
            *(float2*)&Cs[ml * CS_STRIDE + nl] =
                make_float2(acc[mt][nt8][0], acc[mt][nt8][1]);
            *(float2*)&Cs[(ml + 8) * CS_STRIDE + nl] =
                make_float2(acc[mt][nt8][2], acc[mt][nt8][3]);
        }
    __syncthreads();

    // Phase 2: smem -> gmem, coalesced; emit bf16 hi/lo splits for modes 0-3.
    #pragma unroll
    for (int i = 0; i < 16; i++) {
        int idx = tid + i * 256;            // 4096 float4
        int ml = idx >> 5;
        int nl = (idx & 31) * 4;
        float4 v = *(float4*)&Cs[ml * CS_STRIDE + nl];
        int m = m0 + ml, n = n0 + nl;
        int b = m >> 10, t = m & 1023;
        int h = n >> 6, dk = n & 63;
        if (mode == 0) {
            float4 bb = *(const float4*)(bias + n);
            float4 uu = *(const float4*)(ubias + n);
            float4 vv = *(const float4*)(vbias + n);
            float q0f = v.x + bb.x, q1f = v.y + bb.y, q2f = v.z + bb.z, q3f = v.w + bb.w;
            size_t base = ((size_t)(b * H_ + h) * T_ + t) * 128 + dk;
            uint32_t h0, l0, h1, l1;
            split_pack(q0f + uu.x, q1f + uu.y, h0, l0);
            split_pack(q2f + uu.z, q3f + uu.w, h1, l1);
            *(uint2*)(g_Q2h + base) = make_uint2(h0, h1);
            *(uint2*)(g_Q2l + base) = make_uint2(l0, l1);
            split_pack(q0f + vv.x, q1f + vv.y, h0, l0);
            split_pack(q2f + vv.z, q3f + vv.w, h1, l1);
            *(uint2*)(g_Q2h + base + 64) = make_uint2(h0, h1);
            *(uint2*)(g_Q2l + base + 64) = make_uint2(l0, l1);
        } else if (mode == 1 || mode == 2) {
            float4 bb = *(const float4*)(bias + n);
            float x0 = v.x + bb.x, x1 = v.y + bb.y, x2 = v.z + bb.z, x3 = v.w + bb.w;
            size_t base = ((size_t)(b * H_ + h) * T_ + t) * DK_ + dk;
            uint32_t h0, l0, h1, l1;
            split_pack(x0, x1, h0, l0);
            split_pack(x2, x3, h1, l1);
            if (mode == 1) {
                *(uint2*)(g_Kh + base) = make_uint2(h0, h1);
                *(uint2*)(g_Kl + base) = make_uint2(l0, l1);
            } else {
                *(uint2*)(g_Vh + base) = make_uint2(h0, h1);
                *(uint2*)(g_Vl + base) = make_uint2(l0, l1);
            }
        } else if (mode == 3) {
            size_t base = ((size_t)h * T_ + m) * DK_ + dk;   // M=1024 -> m == t
            uint32_t h0, l0, h1, l1;
            split_pack(v.x, v.y, h0, l0);
            split_pack(v.z, v.w, h1, l1);
            *(uint2*)(g_Ph + base) = make_uint2(h0, h1);
            *(uint2*)(g_Pl + base) = make_uint2(l0, l1);
        } else {
            float4 bb = *(const float4*)(bias + n);
            v.x += bb.x; v.y += bb.y; v.z += bb.z; v.w += bb.w;
            *(float4*)(Cout + (size_t)m * D_ + n) = v;
        }
    }
}

// Fused Q/K/V/P projections: blockIdx.z selects mode.
__global__ __launch_bounds__(256, 2) void gemm_qkvp(
    const float* __restrict__ query, const float* __restrict__ key_,
    const float* __restrict__ value, const float* __restrict__ pos_emb,
    const float* __restrict__ Wq, const float* __restrict__ Wk,
    const float* __restrict__ Wv, const float* __restrict__ Wp,
    const float* __restrict__ bq, const float* __restrict__ bk,
    const float* __restrict__ bv,
    const float* __restrict__ pbu, const float* __restrict__ pbv)
{
    extern __shared__ char smem[];
    int mode = blockIdx.z;
    if (mode == 3 && blockIdx.y >= 8) return;   // P: M=1024 only
    const float* A = (mode == 0) ? query : (mode == 1) ? key_
                   : (mode == 2) ? value : pos_emb;
    const float* W = (mode == 0) ? Wq : (mode == 1) ? Wk
                   : (mode == 2) ? Wv : Wp;
    const float* bias = (mode == 0) ? bq : (mode == 1) ? bk : bv;
    gemm_body(smem, smem_u32(smem), A, W, bias, pbu, pbv, nullptr, mode,
              blockIdx.y * 128, blockIdx.x * 128);
}

// Output projection: ctx @ Wo^T + bo
__global__ __launch_bounds__(256, 2) void gemm_out(
    const float* __restrict__ Wo, const float* __restrict__ bo,
    float* __restrict__ Cout)
{
    extern __shared__ char smem[];
    gemm_body(smem, smem_u32(smem), g_ctx, Wo, bo, nullptr, nullptr, Cout, 4,
              blockIdx.y * 128, blockIdx.x * 128);
}

// ---------------------------------------------------------------------------
// Flash attention, mma.sync split-bf16.
// s = ((q+u)*K^T + (q+v)*P^T)/8 + mask_bias; online softmax; O = P@V.
// Block: 128 threads (4 warps, 16 q-rows each), BM=64, BN=64, 16 kt-tiles.
// Q staging smem is reused for K/P/V tiles after fragment extraction.
// ---------------------------------------------------------------------------
#define Q_ROWB 272                      // 136 halves (128 data + 8 pad)
#define K_ROWB 144                      // 72 halves (64 data + 8 pad)
#define AOFF_QH 0                       // staging (dead after frag extraction)
#define AOFF_QL (64 * Q_ROWB)           // 17408; staging ends at 34816
#define AOFF_KH 0
#define AOFF_KL (1 * 64 * K_ROWB)
#define AOFF_PH (2 * 64 * K_ROWB)
#define AOFF_PL (3 * 64 * K_ROWB)
#define AOFF_VH (4 * 64 * K_ROWB)
#define AOFF_VL (5 * 64 * K_ROWB)
#define AOFF_BIAS (6 * 64 * K_ROWB)     // 55296
#define ATTN_SMEM (AOFF_BIAS + 64 * 4)  // 55552 -> 3 blocks/SM (reg-capped)

__global__ __launch_bounds__(128, 3) void attn_kernel(const int* __restrict__ mask)
{
    extern __shared__ char smem[];
    uint32_t sb = smem_u32(smem);
    int tid = threadIdx.x;
    int w = tid >> 5, l = tid & 31;
    int gid = l >> 2, tig = l & 3;
    int bh = blockIdx.y;
    int b = bh >> 3, h = bh & 7;
    int q0 = blockIdx.x * 64;

    // Stage Q2 hi/lo tile (64 rows x 128 halves each) via cp.async
    {
        const __nv_bfloat16* qh = g_Q2h + ((size_t)bh * T_ + q0) * 128;
        const __nv_bfloat16* ql = g_Q2l + ((size_t)bh * T_ + q0) * 128;
        #pragma unroll
        for (int i = 0; i < 8; i++) {
            int lin = tid + i * 128;       // 1024 16B-chunks per array
            int row = lin >> 4, u = lin & 15;
            uint32_t dst = row * Q_ROWB + u * 16;
            cp16(sb + AOFF_QH + dst, qh + row * 128 + u * 8);
            cp16(sb + AOFF_QL + dst, ql + row * 128 + u * 8);
        }
        cp_wait_all();
    }
    __syncthreads();

    // Extract Q fragments for all 4 d-ksteps (live across all kt-tiles)
    uint32_t quh[4][4], qul[4][4], qvh[4][4], qvl[4][4];
    {
        int arow = w * 16 + ((l >> 3) & 1) * 8 + (l & 7);
        int kcb = ((l >> 4) << 3);
        #pragma unroll
        for (int ks = 0; ks < 4; ks++) {
            uint32_t offu = arow * Q_ROWB + (ks * 16 + kcb) * 2;
            uint32_t offv = arow * Q_ROWB + (64 + ks * 16 + kcb) * 2;
            ldm_x4(quh[ks], sb + AOFF_QH + offu);
            ldm_x4(qul[ks], sb + AOFF_QL + offu);
            ldm_x4(qvh[ks], sb + AOFF_QH + offv);
            ldm_x4(qvl[ks], sb + AOFF_QL + offv);
        }
    }
    __syncthreads();   // Q staging region now dead; reuse for K/P/V

    float o[8][4];
    #pragma unroll
    for (int i = 0; i < 8; i++)
        #pragma unroll
        for (int c = 0; c < 4; c++) o[i][c] = 0.f;
    float row_m0 = -1e30f, row_m1 = -1e30f, row_l0 = 0.f, row_l1 = 0.f;

    const __nv_bfloat16* Kh = g_Kh + (size_t)bh * T_ * DK_;
    const __nv_bfloat16* Kl = g_Kl + (size_t)bh * T_ * DK_;
    const __nv_bfloat16* Vh = g_Vh + (size_t)bh * T_ * DK_;
    const __nv_bfloat16* Vl = g_Vl + (size_t)bh * T_ * DK_;
    const __nv_bfloat16* Ph = g_Ph + (size_t)h * T_ * DK_;
    const __nv_bfloat16* Pl = g_Pl + (size_t)h * T_ * DK_;
    const int* mg = mask + b * T_;
    float* sBias = (float*)(smem + AOFF_BIAS);

    for (int k0 = 0; k0 < T_; k0 += 64) {
        // Load K/P/V hi/lo tiles (64 x 64 halves each) via cp.async + mask bias
        #pragma unroll
        for (int i = 0; i < 4; i++) {
            int lin = tid + i * 128;       // 512 16B-chunks per array
            int row = lin >> 3, u = lin & 7;
            size_t src = (size_t)(k0 + row) * DK_ + u * 8;
            uint32_t dst = row * K_ROWB + u * 16;
            cp16(sb + AOFF_KH + dst, Kh + src);
            cp16(sb + AOFF_KL + dst, Kl + src);
            cp16(sb + AOFF_PH + dst, Ph + src);
            cp16(sb + AOFF_PL + dst, Pl + src);
            cp16(sb + AOFF_VH + dst, Vh + src);
            cp16(sb + AOFF_VL + dst, Vl + src);
        }
        if (tid < 64) sBias[tid] = mg[k0 + tid] ? 0.f : -1e30f;
        cp_wait_all();
        __syncthreads();

        // Scores: S(16q x 64kt) per warp
        float s[8][4];
        #pragma unroll
        for (int i = 0; i < 8; i++)
            #pragma unroll
            for (int c = 0; c < 4; c++) s[i][c] = 0.f;

        #pragma unroll
        for (int ks = 0; ks < 4; ks++) {
            #pragma unroll
            for (int nt = 0; nt < 4; nt++) {
                int nrow = nt * 16 + ((l >> 4) << 3) + (l & 7);
                uint32_t boff = nrow * K_ROWB + (ks * 16 + (((l >> 3) & 1) << 3)) * 2;
                uint32_t kbh[4], kbl[4], pbh[4], pbl[4];
                ldm_x4(kbh, sb + AOFF_KH + boff);
                ldm_x4(kbl, sb + AOFF_KL + boff);
                ldm_x4(pbh, sb + AOFF_PH + boff);
                ldm_x4(pbl, sb + AOFF_PL + boff);
                mma_bf16(s[nt * 2],     quh[ks], kbh[0], kbh[1]);
                mma_bf16(s[nt * 2],     quh[ks], kbl[0], kbl[1]);
                mma_bf16(s[nt * 2],     qul[ks], kbh[0], kbh[1]);
                mma_bf16(s[nt * 2],     qvh[ks], pbh[0], pbh[1]);
                mma_bf16(s[nt * 2],     qvh[ks], pbl[0], pbl[1]);
                mma_bf16(s[nt * 2],     qvl[ks], pbh[0], pbh[1]);
                mma_bf16(s[nt * 2 + 1], quh[ks], kbh[2], kbh[3]);
                mma_bf16(s[nt * 2 + 1], quh[ks], kbl[2], kbl[3]);
                mma_bf16(s[nt * 2 + 1], qul[ks], kbh[2], kbh[3]);
                mma_bf16(s[nt * 2 + 1], qvh[ks], pbh[2], pbh[3]);
                mma_bf16(s[nt * 2 + 1], qvh[ks], pbl[2], pbl[3]);
                mma_bf16(s[nt * 2 + 1], qvl[ks], pbh[2], pbh[3]);
            }
        }

        // scale + mask bias, row max (rows gid and gid+8 of this warp's m16)
        float rmax0 = -1e30f, rmax1 = -1e30f;
        #pragma unroll
        for (int nt8 = 0; nt8 < 8; nt8++) {
            int n = nt8 * 8 + tig * 2;
            float b0v = sBias[n], b1v = sBias[n + 1];
            s[nt8][0] = fmaf(s[nt8][0], 0.125f, b0v);
            s[nt8][1] = fmaf(s[nt8][1], 0.125f, b1v);
            s[nt8][2] = fmaf(s[nt8][2], 0.125f, b0v);
            s[nt8][3] = fmaf(s[nt8][3], 0.125f, b1v);
            rmax0 = fmaxf(rmax0, fmaxf(s[nt8][0], s[nt8][1]));
            rmax1 = fmaxf(rmax1, fmaxf(s[nt8][2], s[nt8][3]));
        }
        rmax0 = fmaxf(rmax0, __shfl_xor_sync(0xffffffffu, rmax0, 1));
        rmax0 = fmaxf(rmax0, __shfl_xor_sync(0xffffffffu, rmax0, 2));
        rmax1 = fmaxf(rmax1, __shfl_xor_sync(0xffffffffu, rmax1, 1));
        rmax1 = fmaxf(rmax1, __shfl_xor_sync(0xffffffffu, rmax1, 2));

        float mn0 = fmaxf(row_m0, rmax0), mn1 = fmaxf(row_m1, rmax1);
        float sc0 = fast_exp(row_m0 - mn0), sc1 = fast_exp(row_m1 - mn1);
        float rs0 = 0.f, rs1 = 0.f;
        #pragma unroll
        for (int nt8 = 0; nt8 < 8; nt8++) {
            s[nt8][0] = fast_exp(s[nt8][0] - mn0); rs0 += s[nt8][0];
            s[nt8][1] = fast_exp(s[nt8][1] - mn0); rs0 += s[nt8][1];
            s[nt8][2] = fast_exp(s[nt8][2] - mn1); rs1 += s[nt8][2];
            s[nt8][3] = fast_exp(s[nt8][3] - mn1); rs1 += s[nt8][3];
        }
        rs0 += __shfl_xor_sync(0xffffffffu, rs0, 1);
        rs0 += __shfl_xor_sync(0xffffffffu, rs0, 2);
        rs1 += __shfl_xor_sync(0xffffffffu, rs1, 1);
        rs1 += __shfl_xor_sync(0xffffffffu, rs1, 2);
        row_l0 = row_l0 * sc0 + rs0;
        row_l1 = row_l1 * sc1 + rs1;
        row_m0 = mn0; row_m1 = mn1;

        #pragma unroll
        for (int dt = 0; dt < 8; dt++) {
            o[dt][0] *= sc0; o[dt][1] *= sc0;
            o[dt][2] *= sc1; o[dt][3] *= sc1;
        }

        // probs -> A fragments (hi/lo) for PV; S regs feed A directly
        uint32_t pah[4][4], pal[4][4];
        #pragma unroll
        for (int ks = 0; ks < 4; ks++) {
            split_pack(s[2 * ks][0],     s[2 * ks][1],     pah[ks][0], pal[ks][0]);
            split_pack(s[2 * ks][2],     s[2 * ks][3],     pah[ks][1], pal[ks][1]);
            split_pack(s[2 * ks + 1][0], s[2 * ks + 1][1], pah[ks][2], pal[ks][2]);
            split_pack(s[2 * ks + 1][2], s[2 * ks + 1][3], pah[ks][3], pal[ks][3]);
        }

        // O += P @ V  (V via ldmatrix.trans)
        #pragma unroll
        for (int ks = 0; ks < 4; ks++) {
            int ktrow = ks * 16 + ((l >> 3) & 1) * 8 + (l & 7);
            int dcb = ((l >> 4) << 3);
            #pragma unroll
            for (int dt2 = 0; dt2 < 4; dt2++) {
                uint32_t voff = ktrow * K_ROWB + (dt2 * 16 + dcb) * 2;
                uint32_t vbh[4], vbl[4];
                ldm_x4_t(vbh, sb + AOFF_VH + voff);
                ldm_x4_t(vbl, sb + AOFF_VL + voff);
                mma_bf16(o[dt2 * 2],     pah[ks], vbh[0], vbh[1]);
                mma_bf16(o[dt2 * 2],     pah[ks], vbl[0], vbl[1]);
                mma_bf16(o[dt2 * 2],     pal[ks], vbh[0], vbh[1]);
                mma_bf16(o[dt2 * 2 + 1], pah[ks], vbh[2], vbh[3]);
                mma_bf16(o[dt2 * 2 + 1], pah[ks], vbl[2], vbl[3]);
                mma_bf16(o[dt2 * 2 + 1], pal[ks], vbh[2], vbh[3]);
            }
        }
        __syncthreads();   // done reading this tile; safe to overwrite
    }

    // Epilogue: divide by row sums; write ctx[b, t, h*64+d]
    float rl0 = (row_l0 > 0.f) ? (1.f / row_l0) : 0.f;
    float rl1 = (row_l1 > 0.f) ? (1.f / row_l1) : 0.f;
    int t0 = q0 + w * 16 + gid;
    int t1 = t0 + 8;
    #pragma unroll
    for (int dt = 0; dt < 8; dt++) {
        int d = dt * 8 + tig * 2;
        *(float2*)(g_ctx + ((size_t)b * T_ + t0) * D_ + h * 64 + d) =
            make_float2(o[dt][0] * rl0, o[dt][1] * rl0);
        *(float2*)(g_ctx + ((size_t)b * T_ + t1) * D_ + h * 64 + d) =
            make_float2(o[dt][2] * rl1, o[dt][3] * rl1);
    }
}

// ---------------------------------------------------------------------------
extern "C" void kernel_launch(void* const* d_in, const int* in_sizes, int n_in,
                              void* d_out, int out_size)
{
    (void)in_sizes; (void)n_in; (void)out_size;
    const float* query   = (const float*)d_in[0];
    const float* key_    = (const float*)d_in[1];
    const float* value   = (const float*)d_in[2];
    const int*   mask    = (const int*)  d_in[3];
    const float* pos_emb = (const float*)d_in[4];
    const float* Wq      = (const float*)d_in[5];
    const float* bq      = (const float*)d_in[6];
    const float* Wk      = (const float*)d_in[7];
    const float* bk      = (const float*)d_in[8];
    const float* Wv      = (const float*)d_in[9];
    const float* bv      = (const float*)d_in[10];
    const float* Wp      = (const float*)d_in[11];
    const float* Wo      = (const float*)d_in[12];
    const float* bo      = (const float*)d_in[13];
    const float* pbu     = (const float*)d_in[14];
    const float* pbv     = (const float*)d_in[15];

    cudaFuncSetAttribute(gemm_qkvp,
                         cudaFuncAttributeMaxDynamicSharedMemorySize, GEMM_SMEM);
    cudaFuncSetAttribute(gemm_out,
                         cudaFuncAttributeMaxDynamicSharedMemorySize, GEMM_SMEM);
    cudaFuncSetAttribute(attn_kernel,
                         cudaFuncAttributeMaxDynamicSharedMemorySize, ATTN_SMEM);

    gemm_qkvp<<<dim3(4, 64, 4), 256, GEMM_SMEM>>>(
        query, key_, value, pos_emb, Wq, Wk, Wv, Wp, bq, bk, bv, pbu, pbv);
    attn_kernel<<<dim3(16, 64), 128, ATTN_SMEM>>>(mask);
    gemm_out<<<dim3(4, 64), 256, GEMM_SMEM>>>(Wo, bo, (float*)d_out);
}